// round 10
// baseline (speedup 1.0000x reference)
#include <cuda_runtime.h>
#include <math.h>
#include <stdint.h>

#define N_NODES  4096
#define C_DIM    128
#define H_HEADS  2
#define D_HEAD   64
#define E_EDGES  131072
#define G_GRAPHS 64
#define N_CLASSES 4
#define BN_EPS   1e-5f
#define NSPLIT   4

// ---------------- scratch ----------------------------------------------------
static __device__ float g_h[N_NODES * C_DIM];
static __device__ float g_t2[N_NODES * C_DIM];
static __device__ float g_gcnacc[N_NODES * C_DIM];
static __device__ float g_hl[N_NODES * C_DIM];
static __device__ float g_o[N_NODES * C_DIM];
static __device__ float g_m1[N_NODES * 2 * C_DIM];
static __device__ float g_qkv[N_NODES * 3 * C_DIM];
static __device__ float g_opart[NSPLIT * N_NODES * C_DIM];
static __device__ float g_ml[NSPLIT * N_NODES * H_HEADS * 2];
static __device__ float g_deg[N_NODES];
static __device__ float g_sum[6 * C_DIM];
static __device__ float g_sumsq[6 * C_DIM];
static __device__ float g_pool[G_GRAPHS * C_DIM];
static __device__ float g_cnt[G_GRAPHS];

// ---------------- tf32 / atomic helpers -------------------------------------
__device__ __forceinline__ uint32_t f2tf32(float f) {
    uint32_t u;
    asm volatile("cvt.rna.tf32.f32 %0, %1;\n" : "=r"(u) : "f"(f));
    return u;
}
__device__ __forceinline__ float f2tf32f(float f) {
    return __uint_as_float(f2tf32(f));
}

__device__ __forceinline__ void mma_tf32(float c[4], const uint32_t a[4], const uint32_t b[2]) {
    asm volatile(
        "mma.sync.aligned.m16n8k8.row.col.f32.tf32.tf32.f32 "
        "{%0,%1,%2,%3}, {%4,%5,%6,%7}, {%8,%9}, {%0,%1,%2,%3};\n"
        : "+f"(c[0]), "+f"(c[1]), "+f"(c[2]), "+f"(c[3])
        : "r"(a[0]), "r"(a[1]), "r"(a[2]), "r"(a[3]), "r"(b[0]), "r"(b[1]));
}

__device__ __forceinline__ void red_add_v4(float* p, float a, float b, float c, float d) {
    asm volatile("red.global.add.v4.f32 [%0], {%1,%2,%3,%4};\n"
                 :: "l"(p), "f"(a), "f"(b), "f"(c), "f"(d) : "memory");
}

__device__ __forceinline__ void cp_async16(const float* smem, const float* g) {
    uint32_t s = (uint32_t)__cvta_generic_to_shared(smem);
    asm volatile("cp.async.ca.shared.global [%0], [%1], 16;\n" :: "r"(s), "l"(g));
}
__device__ __forceinline__ void cp_commit() {
    asm volatile("cp.async.commit_group;\n");
}
template <int Np>
__device__ __forceinline__ void cp_wait() {
    asm volatile("cp.async.wait_group %0;\n" :: "n"(Np));
}

#define ML_IDX(sp, row, h) ((((sp) * N_NODES + (row)) * H_HEADS + (h)) * 2)

// ---------------- tensor-core SGEMM (tf32), 8 warps, fused A-modes ----------
// amode 0: A plain. amode 1: A = merged split-KV attention output (from
// g_opart/g_ml, weights in smem). amode 2: A = BN_Abn(A + Ab) + Aadd, side-
// writing Aout (requires K == 128, M == 4096).
#define TSTRIDE 36

__global__ __launch_bounds__(256) void tgemm_kernel(
    const float* __restrict__ A, int lda,
    const float* __restrict__ B, int ldb, int transB,
    float* __restrict__ Cp, int ldc,
    int M, int Nc, int K,
    const float* __restrict__ bias, float alpha, int relu,
    const float* __restrict__ rowdeg,
    float* __restrict__ Cp2, int ldc2,
    const float* __restrict__ statadd, int bnidx,
    int amode,
    const float* __restrict__ Ab, const float* __restrict__ Aadd,
    const float* __restrict__ Agam, const float* __restrict__ Abet,
    int Abn, float* __restrict__ Aout)
{
    __shared__ float As[64 * TSTRIDE];
    __shared__ float Bs[64 * TSTRIDE];
    __shared__ float smw[64 * 8];     // merge weights [row][h][split]

    const int tid  = threadIdx.x;
    const int lane = tid & 31;
    const int w    = tid >> 5;
    const int wm   = w & 3;
    const int wn   = w >> 2;
    const int r    = lane >> 2;
    const int cq   = lane & 3;
    const int m0   = blockIdx.y * 64;
    const int n0   = blockIdx.x * 64;

    if (amode == 1) {
        if (tid < 128) {
            int rl = tid >> 1, hh = tid & 1;
            int rg = m0 + rl;
            float mv[NSPLIT], lv[NSPLIT], mx = -1e30f;
#pragma unroll
            for (int s = 0; s < NSPLIT; s++) {
                int i = ML_IDX(s, rg, hh);
                mv[s] = g_ml[i]; lv[s] = g_ml[i + 1];
                mx = fmaxf(mx, mv[s]);
            }
            float wsum = 0.f, wv[NSPLIT];
#pragma unroll
            for (int s = 0; s < NSPLIT; s++) {
                wv[s] = __expf(mv[s] - mx);
                wsum += wv[s] * lv[s];
            }
            float inv = 1.f / wsum;
#pragma unroll
            for (int s = 0; s < NSPLIT; s++)
                smw[rl * 8 + hh * 4 + s] = wv[s] * inv;
        }
        __syncthreads();
    }

    float acc[4][4];
#pragma unroll
    for (int nt = 0; nt < 4; nt++)
#pragma unroll
        for (int i = 0; i < 4; i++) acc[nt][i] = 0.f;

    for (int k0 = 0; k0 < K; k0 += 32) {
#pragma unroll
        for (int i = 0; i < 8; i++) {
            int idx = tid + i * 256;
            int k = idx & 31, row = idx >> 5;
            int gk = k0 + k;
            float v;
            if (amode == 0) {
                v = (gk < K) ? A[(size_t)(m0 + row) * lda + gk] : 0.f;
            } else if (amode == 1) {
                int hh = gk >> 6;
                const float* bp = g_opart + (size_t)(m0 + row) * C_DIM + gk;
                const float* wp = smw + row * 8 + hh * 4;
                v = bp[0] * wp[0];
#pragma unroll
                for (int s = 1; s < NSPLIT; s++)
                    v += bp[(size_t)s * N_NODES * C_DIM] * wp[s];
            } else {
                size_t ii = (size_t)(m0 + row) * C_DIM + gk;
                float mu  = g_sum[Abn * C_DIM + gk] * (1.f / N_NODES);
                float var = g_sumsq[Abn * C_DIM + gk] * (1.f / N_NODES) - mu * mu;
                float x = A[ii] + Ab[ii];
                v = (x - mu) * rsqrtf(var + BN_EPS) * Agam[gk] + Abet[gk] + Aadd[ii];
                Aout[ii] = v;
            }
            As[row * TSTRIDE + k] = f2tf32f(v);
        }
        if (transB) {
#pragma unroll
            for (int i = 0; i < 8; i++) {
                int idx = tid + i * 256;
                int k = idx & 31, n = idx >> 5;
                int gk = k0 + k;
                float v = (gk < K) ? B[(size_t)(n0 + n) * ldb + gk] : 0.f;
                Bs[n * TSTRIDE + k] = f2tf32f(v);
            }
        } else {
#pragma unroll
            for (int i = 0; i < 8; i++) {
                int idx = tid + i * 256;
                int n = idx & 63, k = idx >> 6;
                int gk = k0 + k;
                float v = (gk < K) ? B[(size_t)gk * ldb + n0 + n] : 0.f;
                Bs[n * TSTRIDE + k] = f2tf32f(v);
            }
        }
        __syncthreads();

        uint32_t a[4][4];
#pragma unroll
        for (int kf = 0; kf < 4; kf++) {
            const float* ar0 = As + (16 * wm + r) * TSTRIDE + 8 * kf;
            const float* ar1 = As + (16 * wm + r + 8) * TSTRIDE + 8 * kf;
            a[kf][0] = __float_as_uint(ar0[cq]);
            a[kf][1] = __float_as_uint(ar1[cq]);
            a[kf][2] = __float_as_uint(ar0[cq + 4]);
            a[kf][3] = __float_as_uint(ar1[cq + 4]);
        }
#pragma unroll
        for (int nt = 0; nt < 4; nt++) {
            const float* br = Bs + (32 * wn + 8 * nt + r) * TSTRIDE;
#pragma unroll
            for (int kf = 0; kf < 4; kf++) {
                uint32_t b[2];
                b[0] = __float_as_uint(br[8 * kf + cq]);
                b[1] = __float_as_uint(br[8 * kf + cq + 4]);
                mma_tf32(acc[nt], a[kf], b);
            }
        }
        __syncthreads();
    }

    int row0 = m0 + 16 * wm + r;
    int row1 = row0 + 8;
    float rs0 = 1.f, rs1 = 1.f;
    if (rowdeg) {
        rs0 = 1.f / rowdeg[row0];
        rs1 = 1.f / rowdeg[row1];
    }

    float csum[4][2], csq[4][2];
#pragma unroll
    for (int nt = 0; nt < 4; nt++) {
        int gn = n0 + 32 * wn + 8 * nt + 2 * cq;
        float p00 = alpha * acc[nt][0];
        float p01 = alpha * acc[nt][1];
        float p10 = alpha * acc[nt][2];
        float p11 = alpha * acc[nt][3];
        if (Cp2) {
            *(float2*)(Cp2 + (size_t)row0 * ldc2 + gn) = make_float2(p00, p01);
            *(float2*)(Cp2 + (size_t)row1 * ldc2 + gn) = make_float2(p10, p11);
        }
        float b0 = bias ? bias[gn] : 0.f;
        float b1 = bias ? bias[gn + 1] : 0.f;
        float v00 = p00 * rs0 + b0;
        float v01 = p01 * rs0 + b1;
        float v10 = p10 * rs1 + b0;
        float v11 = p11 * rs1 + b1;
        if (bnidx >= 0) {
            float2 a0 = *(const float2*)(statadd + (size_t)row0 * 128 + gn);
            float2 a1 = *(const float2*)(statadd + (size_t)row1 * 128 + gn);
            float s00 = v00 + a0.x, s01 = v01 + a0.y;
            float s10 = v10 + a1.x, s11 = v11 + a1.y;
            csum[nt][0] = s00 + s10;
            csum[nt][1] = s01 + s11;
            csq[nt][0]  = s00 * s00 + s10 * s10;
            csq[nt][1]  = s01 * s01 + s11 * s11;
        }
        if (relu) {
            v00 = fmaxf(v00, 0.f); v01 = fmaxf(v01, 0.f);
            v10 = fmaxf(v10, 0.f); v11 = fmaxf(v11, 0.f);
        }
        *(float2*)(Cp + (size_t)row0 * ldc + gn) = make_float2(v00, v01);
        *(float2*)(Cp + (size_t)row1 * ldc + gn) = make_float2(v10, v11);
    }

    if (bnidx >= 0) {
#pragma unroll
        for (int nt = 0; nt < 4; nt++)
#pragma unroll
            for (int j = 0; j < 2; j++) {
#pragma unroll
                for (int msk = 4; msk <= 16; msk <<= 1) {
                    csum[nt][j] += __shfl_xor_sync(0xffffffffu, csum[nt][j], msk);
                    csq[nt][j]  += __shfl_xor_sync(0xffffffffu, csq[nt][j], msk);
                }
            }
        if (lane < 4) {
#pragma unroll
            for (int nt = 0; nt < 4; nt++) {
                int gn = n0 + 32 * wn + 8 * nt + 2 * cq;
                atomicAdd(&g_sum[bnidx * C_DIM + gn],     csum[nt][0]);
                atomicAdd(&g_sum[bnidx * C_DIM + gn + 1], csum[nt][1]);
                atomicAdd(&g_sumsq[bnidx * C_DIM + gn],     csq[nt][0]);
                atomicAdd(&g_sumsq[bnidx * C_DIM + gn + 1], csq[nt][1]);
            }
        }
    }
}

// ---------------- split-KV flash attention (4 splits, 64 q-rows) ------------
#define KSTRIDE 68
#define VSTRIDE 72
#define KSZ (64 * KSTRIDE)
#define VSZ (64 * VSTRIDE)

__global__ __launch_bounds__(128) void flash_attn(
    const float* __restrict__ qkv)
{
    extern __shared__ float sm[];
    float* Kb[2] = { sm, sm + KSZ };
    float* Vb[2] = { sm + 2 * KSZ, sm + 2 * KSZ + VSZ };
    float* Ps    = sm + 2 * KSZ + 2 * VSZ;
    float* Qs    = sm;

    const int tid  = threadIdx.x;
    const int lane = tid & 31;
    const int w    = tid >> 5;
    const int r    = lane >> 2;
    const int cq   = lane & 3;

    const int h    = blockIdx.y;
    const int m0   = blockIdx.x * 64;
    const int sp   = blockIdx.z;
    const int j0   = sp * (64 / NSPLIT);
    const int qoff = h * D_HEAD;
    const int koff = C_DIM + h * D_HEAD;
    const int voff = 2 * C_DIM + h * D_HEAD;

#pragma unroll
    for (int i = 0; i < 8; i++) {
        int idx = tid + i * 128;
        int row = idx >> 4, c4 = idx & 15;
        cp_async16(Qs + row * KSTRIDE + c4 * 4,
                   qkv + (size_t)(m0 + row) * 384 + qoff + c4 * 4);
    }
    cp_commit();
    cp_wait<0>();
    __syncthreads();

    uint32_t qa[8][4];
#pragma unroll
    for (int kf = 0; kf < 8; kf++) {
        const float* qr0 = Qs + (16 * w + r) * KSTRIDE + 8 * kf;
        const float* qr1 = Qs + (16 * w + r + 8) * KSTRIDE + 8 * kf;
        qa[kf][0] = f2tf32(qr0[cq] * 0.125f);
        qa[kf][1] = f2tf32(qr1[cq] * 0.125f);
        qa[kf][2] = f2tf32(qr0[cq + 4] * 0.125f);
        qa[kf][3] = f2tf32(qr1[cq + 4] * 0.125f);
    }
    __syncthreads();

    {
        const float* kg = qkv + (size_t)j0 * 64 * 384 + koff;
        const float* vg = qkv + (size_t)j0 * 64 * 384 + voff;
#pragma unroll
        for (int i = 0; i < 8; i++) {
            int idx = tid + i * 128;
            int row = idx >> 4, c4 = idx & 15;
            cp_async16(Kb[0] + row * KSTRIDE + c4 * 4, kg + (size_t)row * 384 + c4 * 4);
            cp_async16(Vb[0] + row * VSTRIDE + c4 * 4, vg + (size_t)row * 384 + c4 * 4);
        }
        cp_commit();
    }

    float o[8][4];
#pragma unroll
    for (int dt = 0; dt < 8; dt++)
#pragma unroll
        for (int i = 0; i < 4; i++) o[dt][i] = 0.f;
    float mrun0 = -1e30f, mrun1 = -1e30f;
    float lrun0 = 0.f, lrun1 = 0.f;

    const int NBLK = 64 / NSPLIT;
    for (int j = 0; j < NBLK; j++) {
        if (j < NBLK - 1) {
            const float* kg = qkv + (size_t)(j0 + j + 1) * 64 * 384 + koff;
            const float* vg = qkv + (size_t)(j0 + j + 1) * 64 * 384 + voff;
            float* kd = Kb[(j + 1) & 1];
            float* vd = Vb[(j + 1) & 1];
#pragma unroll
            for (int i = 0; i < 8; i++) {
                int idx = tid + i * 128;
                int row = idx >> 4, c4 = idx & 15;
                cp_async16(kd + row * KSTRIDE + c4 * 4, kg + (size_t)row * 384 + c4 * 4);
                cp_async16(vd + row * VSTRIDE + c4 * 4, vg + (size_t)row * 384 + c4 * 4);
            }
            cp_commit();
            cp_wait<1>();
        } else {
            cp_wait<0>();
        }
        __syncthreads();

        const float* Kt = Kb[j & 1];
        const float* Vt = Vb[j & 1];

        float s[8][4];
#pragma unroll
        for (int nt = 0; nt < 8; nt++) {
            s[nt][0] = 0.f; s[nt][1] = 0.f; s[nt][2] = 0.f; s[nt][3] = 0.f;
            const float* kr = Kt + (8 * nt + r) * KSTRIDE;
#pragma unroll
            for (int kf = 0; kf < 8; kf++) {
                uint32_t b[2];
                b[0] = __float_as_uint(kr[8 * kf + cq]);
                b[1] = __float_as_uint(kr[8 * kf + cq + 4]);
                mma_tf32(s[nt], qa[kf], b);
            }
        }

        float mx0 = -1e30f, mx1 = -1e30f;
#pragma unroll
        for (int nt = 0; nt < 8; nt++) {
            mx0 = fmaxf(mx0, fmaxf(s[nt][0], s[nt][1]));
            mx1 = fmaxf(mx1, fmaxf(s[nt][2], s[nt][3]));
        }
        mx0 = fmaxf(mx0, __shfl_xor_sync(0xffffffffu, mx0, 1));
        mx0 = fmaxf(mx0, __shfl_xor_sync(0xffffffffu, mx0, 2));
        mx1 = fmaxf(mx1, __shfl_xor_sync(0xffffffffu, mx1, 1));
        mx1 = fmaxf(mx1, __shfl_xor_sync(0xffffffffu, mx1, 2));

        float mnew0 = fmaxf(mrun0, mx0);
        float mnew1 = fmaxf(mrun1, mx1);
        float f0 = __expf(mrun0 - mnew0);
        float f1 = __expf(mrun1 - mnew1);
        mrun0 = mnew0; mrun1 = mnew1;

        float sum0 = 0.f, sum1 = 0.f;
        float* pw = Ps + (16 * w) * KSTRIDE;
#pragma unroll
        for (int nt = 0; nt < 8; nt++) {
            float p0 = __expf(s[nt][0] - mnew0);
            float p1 = __expf(s[nt][1] - mnew0);
            float p2 = __expf(s[nt][2] - mnew1);
            float p3 = __expf(s[nt][3] - mnew1);
            sum0 += p0 + p1;
            sum1 += p2 + p3;
            float2* d0 = (float2*)(pw + r * KSTRIDE + 8 * nt + 2 * cq);
            float2* d1 = (float2*)(pw + (r + 8) * KSTRIDE + 8 * nt + 2 * cq);
            *d0 = make_float2(f2tf32f(p0), f2tf32f(p1));
            *d1 = make_float2(f2tf32f(p2), f2tf32f(p3));
        }
        sum0 += __shfl_xor_sync(0xffffffffu, sum0, 1);
        sum0 += __shfl_xor_sync(0xffffffffu, sum0, 2);
        sum1 += __shfl_xor_sync(0xffffffffu, sum1, 1);
        sum1 += __shfl_xor_sync(0xffffffffu, sum1, 2);
        lrun0 = lrun0 * f0 + sum0;
        lrun1 = lrun1 * f1 + sum1;

#pragma unroll
        for (int dt = 0; dt < 8; dt++) {
            o[dt][0] *= f0; o[dt][1] *= f0;
            o[dt][2] *= f1; o[dt][3] *= f1;
        }
        __syncwarp();

#pragma unroll
        for (int kf = 0; kf < 8; kf++) {
            uint32_t pa[4];
            pa[0] = __float_as_uint(pw[r * KSTRIDE + 8 * kf + cq]);
            pa[1] = __float_as_uint(pw[(r + 8) * KSTRIDE + 8 * kf + cq]);
            pa[2] = __float_as_uint(pw[r * KSTRIDE + 8 * kf + cq + 4]);
            pa[3] = __float_as_uint(pw[(r + 8) * KSTRIDE + 8 * kf + cq + 4]);
            const float* v0 = Vt + (8 * kf + cq) * VSTRIDE;
            const float* v1 = Vt + (8 * kf + cq + 4) * VSTRIDE;
#pragma unroll
            for (int dt = 0; dt < 8; dt++) {
                uint32_t b[2];
                b[0] = __float_as_uint(v0[8 * dt + r]);
                b[1] = __float_as_uint(v1[8 * dt + r]);
                mma_tf32(o[dt], pa, b);
            }
        }
        __syncthreads();
    }

    int row0 = m0 + 16 * w + r;
    int row1 = row0 + 8;
    float* orow0 = g_opart + (size_t)sp * N_NODES * C_DIM + (size_t)row0 * C_DIM + h * D_HEAD;
    float* orow1 = g_opart + (size_t)sp * N_NODES * C_DIM + (size_t)row1 * C_DIM + h * D_HEAD;
#pragma unroll
    for (int dt = 0; dt < 8; dt++) {
        *(float2*)(orow0 + 8 * dt + 2 * cq) = make_float2(o[dt][0], o[dt][1]);
        *(float2*)(orow1 + 8 * dt + 2 * cq) = make_float2(o[dt][2], o[dt][3]);
    }
    if (cq == 0) {
        int i0 = ML_IDX(sp, row0, h);
        int i1 = ML_IDX(sp, row1, h);
        g_ml[i0] = mrun0; g_ml[i0 + 1] = lrun0;
        g_ml[i1] = mrun1; g_ml[i1 + 1] = lrun1;
    }
}

#define FLASH_SMEM ((2 * KSZ + 2 * VSZ + KSZ) * 4)

// ---------------- init / BN --------------------------------------------------
__global__ void zero_init()
{
    int i = blockIdx.x * blockDim.x + threadIdx.x;
    if (i < 6 * C_DIM) { g_sum[i] = 0.f; g_sumsq[i] = 0.f; }
    if (i < G_GRAPHS * C_DIM) g_pool[i] = 0.f;
    if (i < G_GRAPHS) g_cnt[i] = 0.f;
    if (i < N_NODES) g_deg[i] = 1.f;
}

__global__ void deg_scatter(const int* __restrict__ dst, const int* __restrict__ batch)
{
    int e = blockIdx.x * blockDim.x + threadIdx.x;
    if (e < E_EDGES) atomicAdd(&g_deg[dst[e]], 1.f);
    if (e < N_NODES) atomicAdd(&g_cnt[batch[e]], 1.f);
}

__global__ void bn_stats(const float* __restrict__ a, const float* __restrict__ b, int bn)
{
    int c = threadIdx.x;
    int r0 = blockIdx.x * 32;
    float s = 0.f, s2 = 0.f;
#pragma unroll 4
    for (int r = 0; r < 32; r++) {
        int i = (r0 + r) * C_DIM + c;
        float v = a[i] + b[i];
        s += v; s2 += v * v;
    }
    atomicAdd(&g_sum[bn * C_DIM + c], s);
    atomicAdd(&g_sumsq[bn * C_DIM + c], s2);
}

__global__ void bn_apply(const float* __restrict__ a, const float* __restrict__ b,
                         const float* __restrict__ gamma, const float* __restrict__ beta,
                         float* __restrict__ out, int relu, int bn,
                         const float* __restrict__ addin, float* __restrict__ addout,
                         const int* __restrict__ batch, int dopool)
{
    int t = blockIdx.x * blockDim.x + threadIdx.x;
    if (t >= N_NODES * C_DIM / 4) return;
    int row = t >> 5;
    int c4  = t & 31;
    int c   = c4 * 4;

    float4 va = ((const float4*)a)[t];
    float4 vb = ((const float4*)b)[t];
    float4 vg = *(const float4*)(gamma + c);
    float4 vbt = *(const float4*)(beta + c);
    float4 vsum = *(const float4*)(g_sum + bn * C_DIM + c);
    float4 vsq  = *(const float4*)(g_sumsq + bn * C_DIM + c);

    float4 v;
    {
        float mu, var, rsig, x;
        mu = vsum.x * (1.f / N_NODES); var = vsq.x * (1.f / N_NODES) - mu * mu;
        rsig = rsqrtf(var + BN_EPS); x = va.x + vb.x; v.x = (x - mu) * rsig * vg.x + vbt.x;
        mu = vsum.y * (1.f / N_NODES); var = vsq.y * (1.f / N_NODES) - mu * mu;
        rsig = rsqrtf(var + BN_EPS); x = va.y + vb.y; v.y = (x - mu) * rsig * vg.y + vbt.y;
        mu = vsum.z * (1.f / N_NODES); var = vsq.z * (1.f / N_NODES) - mu * mu;
        rsig = rsqrtf(var + BN_EPS); x = va.z + vb.z; v.z = (x - mu) * rsig * vg.z + vbt.z;
        mu = vsum.w * (1.f / N_NODES); var = vsq.w * (1.f / N_NODES) - mu * mu;
        rsig = rsqrtf(var + BN_EPS); x = va.w + vb.w; v.w = (x - mu) * rsig * vg.w + vbt.w;
    }
    if (relu) {
        v.x = fmaxf(v.x, 0.f); v.y = fmaxf(v.y, 0.f);
        v.z = fmaxf(v.z, 0.f); v.w = fmaxf(v.w, 0.f);
    }
    ((float4*)out)[t] = v;
    if (addout) {
        float4 vi = ((const float4*)addin)[t];
        float4 vo = make_float4(v.x + vi.x, v.y + vi.y, v.z + vi.z, v.w + vi.w);
        ((float4*)addout)[t] = vo;
    }
    if (dopool) {
        int g = batch[row];
        red_add_v4(g_pool + g * C_DIM + c, v.x, v.y, v.z, v.w);
    }
}

// ---------------- GCN --------------------------------------------------------
__global__ void gcn_scatter(const int* __restrict__ src, const int* __restrict__ dst,
                            const float* __restrict__ t1)
{
    int gid = blockIdx.x * blockDim.x + threadIdx.x;
    int e = gid >> 5;
    int lane = gid & 31;
    if (e >= E_EDGES) return;
    int s = src[e], d = dst[e];
    float coef = rsqrtf(g_deg[s]) * rsqrtf(g_deg[d]);
    const float4* hs = (const float4*)(t1 + (size_t)s * C_DIM);
    float* od = g_gcnacc + (size_t)d * C_DIM + lane * 4;
    float4 v = hs[lane];
    red_add_v4(od, v.x * coef, v.y * coef, v.z * coef, v.w * coef);
}

// ---------------- classifier -------------------------------------------------
__global__ void final_kernel(const float* __restrict__ linW,
                             const float* __restrict__ linb,
                             float* __restrict__ out)
{
    __shared__ float sh[C_DIM];
    int g = blockIdx.x;
    int tid = threadIdx.x;
    float cnt = fmaxf(g_cnt[g], 1.f);
    sh[tid] = g_pool[g * C_DIM + tid] / cnt;
    __syncthreads();
    if (tid < N_CLASSES) {
        float acc = linb[tid];
#pragma unroll 4
        for (int c = 0; c < C_DIM; c++)
            acc += sh[c] * linW[c * N_CLASSES + tid];
        out[g * N_CLASSES + tid] = acc;
    }
}

// ---------------- host side --------------------------------------------------
static inline void gemm_s(cudaStream_t st,
                          const float* A, int lda, const float* B, int ldb, int transB,
                          float* Cp, int ldc, int M, int Nc, int K,
                          const float* bias, float alpha, int relu,
                          const float* rowdeg = nullptr,
                          float* Cp2 = nullptr, int ldc2 = 0,
                          const float* statadd = nullptr, int bnidx = -1,
                          int amode = 0,
                          const float* Ab = nullptr, const float* Aadd = nullptr,
                          const float* Agam = nullptr, const float* Abet = nullptr,
                          int Abn = -1, float* Aout = nullptr)
{
    dim3 grid((Nc + 63) / 64, (M + 63) / 64);
    tgemm_kernel<<<grid, 256, 0, st>>>(A, lda, B, ldb, transB, Cp, ldc, M, Nc, K,
                                       bias, alpha, relu, rowdeg, Cp2, ldc2, statadd, bnidx,
                                       amode, Ab, Aadd, Agam, Abet, Abn, Aout);
}

extern "C" void kernel_launch(void* const* d_in, const int* in_sizes, int n_in,
                              void* d_out, int out_size)
{
    const float* x         = (const float*)d_in[0];
    const int*   ei        = (const int*)  d_in[1];
    const int*   batch     = (const int*)  d_in[2];
    const float* proj_W    = (const float*)d_in[3];
    const float* proj_b    = (const float*)d_in[4];
    const float* gcn_W     = (const float*)d_in[5];
    const float* gcn_b     = (const float*)d_in[6];
    const float* qkv_w     = (const float*)d_in[7];
    const float* qkv_b     = (const float*)d_in[8];
    const float* out_w     = (const float*)d_in[9];
    const float* out_b     = (const float*)d_in[10];
    const float* bn_gamma  = (const float*)d_in[11];
    const float* bn_beta   = (const float*)d_in[12];
    const float* mlp_W1    = (const float*)d_in[13];
    const float* mlp_b1    = (const float*)d_in[14];
    const float* mlp_W2    = (const float*)d_in[15];
    const float* mlp_b2    = (const float*)d_in[16];
    const float* lin_W     = (const float*)d_in[17];
    const float* lin_b     = (const float*)d_in[18];
    float*       out       = (float*)d_out;

    const int* e_src = ei;
    const int* e_dst = ei + E_EDGES;

    float *p_h, *p_t2, *p_gcn, *p_hl, *p_o, *p_m1, *p_qkv, *p_deg;
    cudaGetSymbolAddress((void**)&p_h, g_h);
    cudaGetSymbolAddress((void**)&p_t2, g_t2);
    cudaGetSymbolAddress((void**)&p_gcn, g_gcnacc);
    cudaGetSymbolAddress((void**)&p_hl, g_hl);
    cudaGetSymbolAddress((void**)&p_o, g_o);
    cudaGetSymbolAddress((void**)&p_m1, g_m1);
    cudaGetSymbolAddress((void**)&p_qkv, g_qkv);
    cudaGetSymbolAddress((void**)&p_deg, g_deg);

    cudaFuncSetAttribute(flash_attn, cudaFuncAttributeMaxDynamicSharedMemorySize, FLASH_SMEM);

    static cudaStream_t sB = nullptr;
    static cudaEvent_t evFork[2], evJoin[2], evZ;
    if (!sB) {
        cudaStreamCreateWithFlags(&sB, cudaStreamNonBlocking);
        for (int i = 0; i < 2; i++) {
            cudaEventCreateWithFlags(&evFork[i], cudaEventDisableTiming);
            cudaEventCreateWithFlags(&evJoin[i], cudaEventDisableTiming);
        }
        cudaEventCreateWithFlags(&evZ, cudaEventDisableTiming);
    }
    cudaStream_t s0 = 0;

    const int NC4 = N_NODES * C_DIM / 4;

    zero_init<<<(G_GRAPHS * C_DIM + 255) / 256, 256, 0, s0>>>();
    cudaEventRecord(evZ, s0);
    // deg/count scatter on stream B, overlapped with proj GEMM
    cudaStreamWaitEvent(sB, evZ, 0);
    deg_scatter<<<(E_EDGES + 255) / 256, 256, 0, sB>>>(e_dst, batch);

    gemm_s(s0, x, 16, proj_W, C_DIM, 0, p_h, C_DIM, N_NODES, C_DIM, 16, proj_b, 1.f, 0);

    for (int l = 0; l < 2; l++) {
        const float* W_gcn  = gcn_W + (size_t)l * C_DIM * C_DIM;
        const float* b_gcn  = gcn_b + l * C_DIM;
        const float* W_qkv  = qkv_w + (size_t)l * 3 * C_DIM * C_DIM;
        const float* b_qkv  = qkv_b + l * 3 * C_DIM;
        const float* W_out  = out_w + (size_t)l * C_DIM * C_DIM;
        const float* b_out  = out_b + l * C_DIM;
        const float* W1     = mlp_W1 + (size_t)l * C_DIM * 2 * C_DIM;
        const float* b1     = mlp_b1 + l * 2 * C_DIM;
        const float* W2     = mlp_W2 + (size_t)l * 2 * C_DIM * C_DIM;
        const float* b2     = mlp_b2 + l * C_DIM;
        const float* gam    = bn_gamma + (size_t)l * 3 * C_DIM;
        const float* bet    = bn_beta  + (size_t)l * 3 * C_DIM;
        int bn0 = l * 3, bn1 = l * 3 + 1, bn2 = l * 3 + 2;

        // ==== fork ====
        cudaEventRecord(evFork[l], s0);
        cudaStreamWaitEvent(sB, evFork[l], 0);

        // ---- GCN branch (stream B)
        gemm_s(sB, p_h, C_DIM, W_gcn, C_DIM, 0, p_gcn, C_DIM, N_NODES, C_DIM, C_DIM,
               b_gcn, 1.f, 0, p_deg, p_m1, C_DIM);
        gcn_scatter<<<(E_EDGES * 32) / 256, 256, 0, sB>>>(e_src, e_dst, p_m1);
        bn_stats<<<N_NODES / 32, 128, 0, sB>>>(p_gcn, p_h, bn0);
        bn_apply<<<(NC4 + 255) / 256, 256, 0, sB>>>(p_gcn, p_h, gam, bet, p_hl, 0, bn0,
                                                    nullptr, nullptr, nullptr, 0);
        cudaEventRecord(evJoin[l], sB);

        // ---- MHA branch (stream 0)
        gemm_s(s0, p_h, C_DIM, W_qkv, C_DIM, 1, p_qkv, 3 * C_DIM, N_NODES, 3 * C_DIM, C_DIM,
               b_qkv, 1.f, 0);
        flash_attn<<<dim3(64, 2, NSPLIT), 128, FLASH_SMEM, s0>>>(p_qkv);
        // out-proj GEMM: A = merged attention output (amode 1); bn1 stats fused
        gemm_s(s0, nullptr, 0, W_out, C_DIM, 1, p_t2, C_DIM, N_NODES, C_DIM, C_DIM,
               b_out, 1.f, 0, nullptr, nullptr, 0, p_h, bn1, /*amode=*/1);

        // ==== join (hl needed by fused W1 A-load) ====
        cudaStreamWaitEvent(s0, evJoin[l], 0);

        // ---- MLP: W1 GEMM with fused bn1-apply A-mode (A = BN1(t2+h)+hl, writes o)
        gemm_s(s0, p_t2, C_DIM, W1, 2 * C_DIM, 0, p_m1, 2 * C_DIM, N_NODES, 2 * C_DIM, C_DIM,
               b1, 1.f, 1, nullptr, nullptr, 0, nullptr, -1,
               /*amode=*/2, p_h, p_hl, gam + C_DIM, bet + C_DIM, bn1, p_o);
        gemm_s(s0, p_m1, 2 * C_DIM, W2, C_DIM, 0, p_t2, C_DIM, N_NODES, C_DIM, 2 * C_DIM,
               b2, 1.f, 0, nullptr, nullptr, 0, p_o, bn2);
        bn_apply<<<(NC4 + 255) / 256, 256, 0, s0>>>(p_o, p_t2, gam + 2 * C_DIM, bet + 2 * C_DIM, p_h,
                                                    l == 0 ? 1 : 0, bn2,
                                                    nullptr, nullptr, batch, l == 1 ? 1 : 0);
    }

    final_kernel<<<G_GRAPHS, C_DIM, 0, s0>>>(lin_W, lin_b, out);
}

// round 11
// speedup vs baseline: 1.2593x; 1.2593x over previous
#include <cuda_runtime.h>
#include <math.h>
#include <stdint.h>

#define N_NODES  4096
#define C_DIM    128
#define H_HEADS  2
#define D_HEAD   64
#define E_EDGES  131072
#define G_GRAPHS 64
#define N_CLASSES 4
#define BN_EPS   1e-5f
#define NSPLIT   4

// ---------------- scratch ----------------------------------------------------
static __device__ float g_h[N_NODES * C_DIM];
static __device__ float g_t2[N_NODES * C_DIM];
static __device__ float g_gcnacc[N_NODES * C_DIM];
static __device__ float g_hl[N_NODES * C_DIM];
static __device__ float g_ha[N_NODES * C_DIM];
static __device__ float g_o[N_NODES * C_DIM];
static __device__ float g_m1[N_NODES * 2 * C_DIM];
static __device__ float g_qkv[N_NODES * 3 * C_DIM];
static __device__ float g_attno[N_NODES * C_DIM];
static __device__ float g_opart[NSPLIT * N_NODES * C_DIM];
static __device__ float g_ml[NSPLIT * N_NODES * H_HEADS * 2];
static __device__ float g_deg[N_NODES];
static __device__ float g_sum[6 * C_DIM];
static __device__ float g_sumsq[6 * C_DIM];
static __device__ float g_pool[G_GRAPHS * C_DIM];
static __device__ float g_cnt[G_GRAPHS];

// ---------------- tf32 / atomic helpers -------------------------------------
__device__ __forceinline__ uint32_t f2tf32(float f) {
    uint32_t u;
    asm volatile("cvt.rna.tf32.f32 %0, %1;\n" : "=r"(u) : "f"(f));
    return u;
}
__device__ __forceinline__ float f2tf32f(float f) {
    return __uint_as_float(f2tf32(f));
}

__device__ __forceinline__ void mma_tf32(float c[4], const uint32_t a[4], const uint32_t b[2]) {
    asm volatile(
        "mma.sync.aligned.m16n8k8.row.col.f32.tf32.tf32.f32 "
        "{%0,%1,%2,%3}, {%4,%5,%6,%7}, {%8,%9}, {%0,%1,%2,%3};\n"
        : "+f"(c[0]), "+f"(c[1]), "+f"(c[2]), "+f"(c[3])
        : "r"(a[0]), "r"(a[1]), "r"(a[2]), "r"(a[3]), "r"(b[0]), "r"(b[1]));
}

__device__ __forceinline__ void red_add_v4(float* p, float a, float b, float c, float d) {
    asm volatile("red.global.add.v4.f32 [%0], {%1,%2,%3,%4};\n"
                 :: "l"(p), "f"(a), "f"(b), "f"(c), "f"(d) : "memory");
}

__device__ __forceinline__ void cp_async16(const float* smem, const float* g) {
    uint32_t s = (uint32_t)__cvta_generic_to_shared(smem);
    asm volatile("cp.async.ca.shared.global [%0], [%1], 16;\n" :: "r"(s), "l"(g));
}
__device__ __forceinline__ void cp_commit() {
    asm volatile("cp.async.commit_group;\n");
}
template <int Np>
__device__ __forceinline__ void cp_wait() {
    asm volatile("cp.async.wait_group %0;\n" :: "n"(Np));
}

// ---------------- tensor-core SGEMM (tf32), 8 warps --------------------------
#define TSTRIDE 36

__global__ __launch_bounds__(256) void tgemm_kernel(
    const float* __restrict__ A, int lda,
    const float* __restrict__ B, int ldb, int transB,
    float* __restrict__ Cp, int ldc,
    int M, int Nc, int K,
    const float* __restrict__ bias, float alpha, int relu,
    const float* __restrict__ rowdeg,
    float* __restrict__ Cp2, int ldc2,
    const float* __restrict__ statadd, int bnidx)
{
    __shared__ float As[64 * TSTRIDE];
    __shared__ float Bs[64 * TSTRIDE];

    const int tid  = threadIdx.x;
    const int lane = tid & 31;
    const int w    = tid >> 5;
    const int wm   = w & 3;
    const int wn   = w >> 2;
    const int r    = lane >> 2;
    const int cq   = lane & 3;
    const int m0   = blockIdx.y * 64;
    const int n0   = blockIdx.x * 64;

    float acc[4][4];
#pragma unroll
    for (int nt = 0; nt < 4; nt++)
#pragma unroll
        for (int i = 0; i < 4; i++) acc[nt][i] = 0.f;

    for (int k0 = 0; k0 < K; k0 += 32) {
#pragma unroll
        for (int i = 0; i < 8; i++) {
            int idx = tid + i * 256;
            int k = idx & 31, row = idx >> 5;
            int gk = k0 + k;
            float v = (gk < K) ? A[(size_t)(m0 + row) * lda + gk] : 0.f;
            As[row * TSTRIDE + k] = f2tf32f(v);
        }
        if (transB) {
#pragma unroll
            for (int i = 0; i < 8; i++) {
                int idx = tid + i * 256;
                int k = idx & 31, n = idx >> 5;
                int gk = k0 + k;
                float v = (gk < K) ? B[(size_t)(n0 + n) * ldb + gk] : 0.f;
                Bs[n * TSTRIDE + k] = f2tf32f(v);
            }
        } else {
#pragma unroll
            for (int i = 0; i < 8; i++) {
                int idx = tid + i * 256;
                int n = idx & 63, k = idx >> 6;
                int gk = k0 + k;
                float v = (gk < K) ? B[(size_t)gk * ldb + n0 + n] : 0.f;
                Bs[n * TSTRIDE + k] = f2tf32f(v);
            }
        }
        __syncthreads();

        uint32_t a[4][4];
#pragma unroll
        for (int kf = 0; kf < 4; kf++) {
            const float* ar0 = As + (16 * wm + r) * TSTRIDE + 8 * kf;
            const float* ar1 = As + (16 * wm + r + 8) * TSTRIDE + 8 * kf;
            a[kf][0] = __float_as_uint(ar0[cq]);
            a[kf][1] = __float_as_uint(ar1[cq]);
            a[kf][2] = __float_as_uint(ar0[cq + 4]);
            a[kf][3] = __float_as_uint(ar1[cq + 4]);
        }
#pragma unroll
        for (int nt = 0; nt < 4; nt++) {
            const float* br = Bs + (32 * wn + 8 * nt + r) * TSTRIDE;
#pragma unroll
            for (int kf = 0; kf < 4; kf++) {
                uint32_t b[2];
                b[0] = __float_as_uint(br[8 * kf + cq]);
                b[1] = __float_as_uint(br[8 * kf + cq + 4]);
                mma_tf32(acc[nt], a[kf], b);
            }
        }
        __syncthreads();
    }

    int row0 = m0 + 16 * wm + r;
    int row1 = row0 + 8;
    float rs0 = 1.f, rs1 = 1.f;
    if (rowdeg) {
        rs0 = 1.f / rowdeg[row0];
        rs1 = 1.f / rowdeg[row1];
    }

    float csum[4][2], csq[4][2];
#pragma unroll
    for (int nt = 0; nt < 4; nt++) {
        int gn = n0 + 32 * wn + 8 * nt + 2 * cq;
        float p00 = alpha * acc[nt][0];
        float p01 = alpha * acc[nt][1];
        float p10 = alpha * acc[nt][2];
        float p11 = alpha * acc[nt][3];
        if (Cp2) {
            *(float2*)(Cp2 + (size_t)row0 * ldc2 + gn) = make_float2(p00, p01);
            *(float2*)(Cp2 + (size_t)row1 * ldc2 + gn) = make_float2(p10, p11);
        }
        float b0 = bias ? bias[gn] : 0.f;
        float b1 = bias ? bias[gn + 1] : 0.f;
        float v00 = p00 * rs0 + b0;
        float v01 = p01 * rs0 + b1;
        float v10 = p10 * rs1 + b0;
        float v11 = p11 * rs1 + b1;
        if (bnidx >= 0) {
            float2 a0 = *(const float2*)(statadd + (size_t)row0 * 128 + gn);
            float2 a1 = *(const float2*)(statadd + (size_t)row1 * 128 + gn);
            float s00 = v00 + a0.x, s01 = v01 + a0.y;
            float s10 = v10 + a1.x, s11 = v11 + a1.y;
            csum[nt][0] = s00 + s10;
            csum[nt][1] = s01 + s11;
            csq[nt][0]  = s00 * s00 + s10 * s10;
            csq[nt][1]  = s01 * s01 + s11 * s11;
        }
        if (relu) {
            v00 = fmaxf(v00, 0.f); v01 = fmaxf(v01, 0.f);
            v10 = fmaxf(v10, 0.f); v11 = fmaxf(v11, 0.f);
        }
        *(float2*)(Cp + (size_t)row0 * ldc + gn) = make_float2(v00, v01);
        *(float2*)(Cp + (size_t)row1 * ldc + gn) = make_float2(v10, v11);
    }

    if (bnidx >= 0) {
#pragma unroll
        for (int nt = 0; nt < 4; nt++)
#pragma unroll
            for (int j = 0; j < 2; j++) {
#pragma unroll
                for (int msk = 4; msk <= 16; msk <<= 1) {
                    csum[nt][j] += __shfl_xor_sync(0xffffffffu, csum[nt][j], msk);
                    csq[nt][j]  += __shfl_xor_sync(0xffffffffu, csq[nt][j], msk);
                }
            }
        if (lane < 4) {
#pragma unroll
            for (int nt = 0; nt < 4; nt++) {
                int gn = n0 + 32 * wn + 8 * nt + 2 * cq;
                atomicAdd(&g_sum[bnidx * C_DIM + gn],     csum[nt][0]);
                atomicAdd(&g_sum[bnidx * C_DIM + gn + 1], csum[nt][1]);
                atomicAdd(&g_sumsq[bnidx * C_DIM + gn],     csq[nt][0]);
                atomicAdd(&g_sumsq[bnidx * C_DIM + gn + 1], csq[nt][1]);
            }
        }
    }
}

// ---------------- split-KV flash attention (4 splits, 64 q-rows) ------------
#define KSTRIDE 68
#define VSTRIDE 72
#define KSZ (64 * KSTRIDE)
#define VSZ (64 * VSTRIDE)
#define ML_IDX(sp, row, h) ((((sp) * N_NODES + (row)) * H_HEADS + (h)) * 2)

__global__ __launch_bounds__(128) void flash_attn(
    const float* __restrict__ qkv)
{
    extern __shared__ float sm[];
    float* Kb[2] = { sm, sm + KSZ };
    float* Vb[2] = { sm + 2 * KSZ, sm + 2 * KSZ + VSZ };
    float* Ps    = sm + 2 * KSZ + 2 * VSZ;
    float* Qs    = sm;

    const int tid  = threadIdx.x;
    const int lane = tid & 31;
    const int w    = tid >> 5;
    const int r    = lane >> 2;
    const int cq   = lane & 3;

    const int h    = blockIdx.y;
    const int m0   = blockIdx.x * 64;
    const int sp   = blockIdx.z;
    const int j0   = sp * (64 / NSPLIT);
    const int qoff = h * D_HEAD;
    const int koff = C_DIM + h * D_HEAD;
    const int voff = 2 * C_DIM + h * D_HEAD;

#pragma unroll
    for (int i = 0; i < 8; i++) {
        int idx = tid + i * 128;
        int row = idx >> 4, c4 = idx & 15;
        cp_async16(Qs + row * KSTRIDE + c4 * 4,
                   qkv + (size_t)(m0 + row) * 384 + qoff + c4 * 4);
    }
    cp_commit();
    cp_wait<0>();
    __syncthreads();

    uint32_t qa[8][4];
#pragma unroll
    for (int kf = 0; kf < 8; kf++) {
        const float* qr0 = Qs + (16 * w + r) * KSTRIDE + 8 * kf;
        const float* qr1 = Qs + (16 * w + r + 8) * KSTRIDE + 8 * kf;
        qa[kf][0] = f2tf32(qr0[cq] * 0.125f);
        qa[kf][1] = f2tf32(qr1[cq] * 0.125f);
        qa[kf][2] = f2tf32(qr0[cq + 4] * 0.125f);
        qa[kf][3] = f2tf32(qr1[cq + 4] * 0.125f);
    }
    __syncthreads();

    {
        const float* kg = qkv + (size_t)j0 * 64 * 384 + koff;
        const float* vg = qkv + (size_t)j0 * 64 * 384 + voff;
#pragma unroll
        for (int i = 0; i < 8; i++) {
            int idx = tid + i * 128;
            int row = idx >> 4, c4 = idx & 15;
            cp_async16(Kb[0] + row * KSTRIDE + c4 * 4, kg + (size_t)row * 384 + c4 * 4);
            cp_async16(Vb[0] + row * VSTRIDE + c4 * 4, vg + (size_t)row * 384 + c4 * 4);
        }
        cp_commit();
    }

    float o[8][4];
#pragma unroll
    for (int dt = 0; dt < 8; dt++)
#pragma unroll
        for (int i = 0; i < 4; i++) o[dt][i] = 0.f;
    float mrun0 = -1e30f, mrun1 = -1e30f;
    float lrun0 = 0.f, lrun1 = 0.f;

    const int NBLK = 64 / NSPLIT;
    for (int j = 0; j < NBLK; j++) {
        if (j < NBLK - 1) {
            const float* kg = qkv + (size_t)(j0 + j + 1) * 64 * 384 + koff;
            const float* vg = qkv + (size_t)(j0 + j + 1) * 64 * 384 + voff;
            float* kd = Kb[(j + 1) & 1];
            float* vd = Vb[(j + 1) & 1];
#pragma unroll
            for (int i = 0; i < 8; i++) {
                int idx = tid + i * 128;
                int row = idx >> 4, c4 = idx & 15;
                cp_async16(kd + row * KSTRIDE + c4 * 4, kg + (size_t)row * 384 + c4 * 4);
                cp_async16(vd + row * VSTRIDE + c4 * 4, vg + (size_t)row * 384 + c4 * 4);
            }
            cp_commit();
            cp_wait<1>();
        } else {
            cp_wait<0>();
        }
        __syncthreads();

        const float* Kt = Kb[j & 1];
        const float* Vt = Vb[j & 1];

        float s[8][4];
#pragma unroll
        for (int nt = 0; nt < 8; nt++) {
            s[nt][0] = 0.f; s[nt][1] = 0.f; s[nt][2] = 0.f; s[nt][3] = 0.f;
            const float* kr = Kt + (8 * nt + r) * KSTRIDE;
#pragma unroll
            for (int kf = 0; kf < 8; kf++) {
                uint32_t b[2];
                b[0] = __float_as_uint(kr[8 * kf + cq]);
                b[1] = __float_as_uint(kr[8 * kf + cq + 4]);
                mma_tf32(s[nt], qa[kf], b);
            }
        }

        float mx0 = -1e30f, mx1 = -1e30f;
#pragma unroll
        for (int nt = 0; nt < 8; nt++) {
            mx0 = fmaxf(mx0, fmaxf(s[nt][0], s[nt][1]));
            mx1 = fmaxf(mx1, fmaxf(s[nt][2], s[nt][3]));
        }
        mx0 = fmaxf(mx0, __shfl_xor_sync(0xffffffffu, mx0, 1));
        mx0 = fmaxf(mx0, __shfl_xor_sync(0xffffffffu, mx0, 2));
        mx1 = fmaxf(mx1, __shfl_xor_sync(0xffffffffu, mx1, 1));
        mx1 = fmaxf(mx1, __shfl_xor_sync(0xffffffffu, mx1, 2));

        float mnew0 = fmaxf(mrun0, mx0);
        float mnew1 = fmaxf(mrun1, mx1);
        float f0 = __expf(mrun0 - mnew0);
        float f1 = __expf(mrun1 - mnew1);
        mrun0 = mnew0; mrun1 = mnew1;

        float sum0 = 0.f, sum1 = 0.f;
        float* pw = Ps + (16 * w) * KSTRIDE;
#pragma unroll
        for (int nt = 0; nt < 8; nt++) {
            float p0 = __expf(s[nt][0] - mnew0);
            float p1 = __expf(s[nt][1] - mnew0);
            float p2 = __expf(s[nt][2] - mnew1);
            float p3 = __expf(s[nt][3] - mnew1);
            sum0 += p0 + p1;
            sum1 += p2 + p3;
            float2* d0 = (float2*)(pw + r * KSTRIDE + 8 * nt + 2 * cq);
            float2* d1 = (float2*)(pw + (r + 8) * KSTRIDE + 8 * nt + 2 * cq);
            *d0 = make_float2(f2tf32f(p0), f2tf32f(p1));
            *d1 = make_float2(f2tf32f(p2), f2tf32f(p3));
        }
        sum0 += __shfl_xor_sync(0xffffffffu, sum0, 1);
        sum0 += __shfl_xor_sync(0xffffffffu, sum0, 2);
        sum1 += __shfl_xor_sync(0xffffffffu, sum1, 1);
        sum1 += __shfl_xor_sync(0xffffffffu, sum1, 2);
        lrun0 = lrun0 * f0 + sum0;
        lrun1 = lrun1 * f1 + sum1;

#pragma unroll
        for (int dt = 0; dt < 8; dt++) {
            o[dt][0] *= f0; o[dt][1] *= f0;
            o[dt][2] *= f1; o[dt][3] *= f1;
        }
        __syncwarp();

#pragma unroll
        for (int kf = 0; kf < 8; kf++) {
            uint32_t pa[4];
            pa[0] = __float_as_uint(pw[r * KSTRIDE + 8 * kf + cq]);
            pa[1] = __float_as_uint(pw[(r + 8) * KSTRIDE + 8 * kf + cq]);
            pa[2] = __float_as_uint(pw[r * KSTRIDE + 8 * kf + cq + 4]);
            pa[3] = __float_as_uint(pw[(r + 8) * KSTRIDE + 8 * kf + cq + 4]);
            const float* v0 = Vt + (8 * kf + cq) * VSTRIDE;
            const float* v1 = Vt + (8 * kf + cq + 4) * VSTRIDE;
#pragma unroll
            for (int dt = 0; dt < 8; dt++) {
                uint32_t b[2];
                b[0] = __float_as_uint(v0[8 * dt + r]);
                b[1] = __float_as_uint(v1[8 * dt + r]);
                mma_tf32(o[dt], pa, b);
            }
        }
        __syncthreads();
    }

    int row0 = m0 + 16 * w + r;
    int row1 = row0 + 8;
    float* orow0 = g_opart + (size_t)sp * N_NODES * C_DIM + (size_t)row0 * C_DIM + h * D_HEAD;
    float* orow1 = g_opart + (size_t)sp * N_NODES * C_DIM + (size_t)row1 * C_DIM + h * D_HEAD;
#pragma unroll
    for (int dt = 0; dt < 8; dt++) {
        *(float2*)(orow0 + 8 * dt + 2 * cq) = make_float2(o[dt][0], o[dt][1]);
        *(float2*)(orow1 + 8 * dt + 2 * cq) = make_float2(o[dt][2], o[dt][3]);
    }
    if (cq == 0) {
        int i0 = ML_IDX(sp, row0, h);
        int i1 = ML_IDX(sp, row1, h);
        g_ml[i0] = mrun0; g_ml[i0 + 1] = lrun0;
        g_ml[i1] = mrun1; g_ml[i1 + 1] = lrun1;
    }
}

#define FLASH_SMEM ((2 * KSZ + 2 * VSZ + KSZ) * 4)

// merge NSPLIT KV splits (exact fp32)
__global__ void merge_attn()
{
    int t = blockIdx.x * blockDim.x + threadIdx.x;
    if (t >= N_NODES * C_DIM / 4) return;
    int row = t >> 5;
    int c4  = t & 31;
    int h   = c4 >> 4;

    float m = -1e30f;
    float mv[NSPLIT], lv[NSPLIT];
#pragma unroll
    for (int s = 0; s < NSPLIT; s++) {
        int i = ML_IDX(s, row, h);
        mv[s] = g_ml[i]; lv[s] = g_ml[i + 1];
        m = fmaxf(m, mv[s]);
    }
    float wsum = 0.f, wv[NSPLIT];
#pragma unroll
    for (int s = 0; s < NSPLIT; s++) {
        wv[s] = __expf(mv[s] - m);
        wsum += wv[s] * lv[s];
    }
    float inv = 1.f / wsum;

    float4 acc = make_float4(0.f, 0.f, 0.f, 0.f);
#pragma unroll
    for (int s = 0; s < NSPLIT; s++) {
        float4 ov = ((const float4*)(g_opart + (size_t)s * N_NODES * C_DIM + (size_t)row * C_DIM))[c4];
        acc.x += wv[s] * ov.x;
        acc.y += wv[s] * ov.y;
        acc.z += wv[s] * ov.z;
        acc.w += wv[s] * ov.w;
    }
    acc.x *= inv; acc.y *= inv; acc.z *= inv; acc.w *= inv;
    ((float4*)(g_attno + (size_t)row * C_DIM))[c4] = acc;
}

// ---------------- init / BN --------------------------------------------------
__global__ void zero_init()
{
    int i = blockIdx.x * blockDim.x + threadIdx.x;
    if (i < 6 * C_DIM) { g_sum[i] = 0.f; g_sumsq[i] = 0.f; }
    if (i < G_GRAPHS * C_DIM) g_pool[i] = 0.f;
    if (i < G_GRAPHS) g_cnt[i] = 0.f;
    if (i < N_NODES) g_deg[i] = 1.f;
}

__global__ void deg_scatter(const int* __restrict__ dst, const int* __restrict__ batch)
{
    int e = blockIdx.x * blockDim.x + threadIdx.x;
    if (e < E_EDGES) atomicAdd(&g_deg[dst[e]], 1.f);
    if (e < N_NODES) atomicAdd(&g_cnt[batch[e]], 1.f);
}

__global__ void bn_stats(const float* __restrict__ a, const float* __restrict__ b, int bn)
{
    int c = threadIdx.x;
    int r0 = blockIdx.x * 32;
    float s = 0.f, s2 = 0.f;
#pragma unroll 4
    for (int r = 0; r < 32; r++) {
        int i = (r0 + r) * C_DIM + c;
        float v = a[i] + b[i];
        s += v; s2 += v * v;
    }
    atomicAdd(&g_sum[bn * C_DIM + c], s);
    atomicAdd(&g_sumsq[bn * C_DIM + c], s2);
}

__global__ void bn_apply(const float* __restrict__ a, const float* __restrict__ b,
                         const float* __restrict__ gamma, const float* __restrict__ beta,
                         float* __restrict__ out, int relu, int bn,
                         const float* __restrict__ addin, float* __restrict__ addout,
                         const int* __restrict__ batch, int dopool)
{
    int t = blockIdx.x * blockDim.x + threadIdx.x;
    if (t >= N_NODES * C_DIM / 4) return;
    int row = t >> 5;
    int c4  = t & 31;
    int c   = c4 * 4;

    float4 va = ((const float4*)a)[t];
    float4 vb = ((const float4*)b)[t];
    float4 vg = *(const float4*)(gamma + c);
    float4 vbt = *(const float4*)(beta + c);
    float4 vsum = *(const float4*)(g_sum + bn * C_DIM + c);
    float4 vsq  = *(const float4*)(g_sumsq + bn * C_DIM + c);

    float4 v;
    {
        float mu, var, rsig, x;
        mu = vsum.x * (1.f / N_NODES); var = vsq.x * (1.f / N_NODES) - mu * mu;
        rsig = rsqrtf(var + BN_EPS); x = va.x + vb.x; v.x = (x - mu) * rsig * vg.x + vbt.x;
        mu = vsum.y * (1.f / N_NODES); var = vsq.y * (1.f / N_NODES) - mu * mu;
        rsig = rsqrtf(var + BN_EPS); x = va.y + vb.y; v.y = (x - mu) * rsig * vg.y + vbt.y;
        mu = vsum.z * (1.f / N_NODES); var = vsq.z * (1.f / N_NODES) - mu * mu;
        rsig = rsqrtf(var + BN_EPS); x = va.z + vb.z; v.z = (x - mu) * rsig * vg.z + vbt.z;
        mu = vsum.w * (1.f / N_NODES); var = vsq.w * (1.f / N_NODES) - mu * mu;
        rsig = rsqrtf(var + BN_EPS); x = va.w + vb.w; v.w = (x - mu) * rsig * vg.w + vbt.w;
    }
    if (relu) {
        v.x = fmaxf(v.x, 0.f); v.y = fmaxf(v.y, 0.f);
        v.z = fmaxf(v.z, 0.f); v.w = fmaxf(v.w, 0.f);
    }
    ((float4*)out)[t] = v;
    if (addout) {
        float4 vi = ((const float4*)addin)[t];
        float4 vo = make_float4(v.x + vi.x, v.y + vi.y, v.z + vi.z, v.w + vi.w);
        ((float4*)addout)[t] = vo;
    }
    if (dopool) {
        int g = batch[row];
        red_add_v4(g_pool + g * C_DIM + c, v.x, v.y, v.z, v.w);
    }
}

// ---------------- GCN --------------------------------------------------------
__global__ void gcn_scatter(const int* __restrict__ src, const int* __restrict__ dst,
                            const float* __restrict__ t1)
{
    int gid = blockIdx.x * blockDim.x + threadIdx.x;
    int e = gid >> 5;
    int lane = gid & 31;
    if (e >= E_EDGES) return;
    int s = src[e], d = dst[e];
    float coef = rsqrtf(g_deg[s]) * rsqrtf(g_deg[d]);
    const float4* hs = (const float4*)(t1 + (size_t)s * C_DIM);
    float* od = g_gcnacc + (size_t)d * C_DIM + lane * 4;
    float4 v = hs[lane];
    red_add_v4(od, v.x * coef, v.y * coef, v.z * coef, v.w * coef);
}

// ---------------- classifier -------------------------------------------------
__global__ void final_kernel(const float* __restrict__ linW,
                             const float* __restrict__ linb,
                             float* __restrict__ out)
{
    __shared__ float sh[C_DIM];
    int g = blockIdx.x;
    int tid = threadIdx.x;
    float cnt = fmaxf(g_cnt[g], 1.f);
    sh[tid] = g_pool[g * C_DIM + tid] / cnt;
    __syncthreads();
    if (tid < N_CLASSES) {
        float acc = linb[tid];
#pragma unroll 4
        for (int c = 0; c < C_DIM; c++)
            acc += sh[c] * linW[c * N_CLASSES + tid];
        out[g * N_CLASSES + tid] = acc;
    }
}

// ---------------- host side --------------------------------------------------
static inline void gemm_s(cudaStream_t st,
                          const float* A, int lda, const float* B, int ldb, int transB,
                          float* Cp, int ldc, int M, int Nc, int K,
                          const float* bias, float alpha, int relu,
                          const float* rowdeg = nullptr,
                          float* Cp2 = nullptr, int ldc2 = 0,
                          const float* statadd = nullptr, int bnidx = -1)
{
    dim3 grid((Nc + 63) / 64, (M + 63) / 64);
    tgemm_kernel<<<grid, 256, 0, st>>>(A, lda, B, ldb, transB, Cp, ldc, M, Nc, K,
                                       bias, alpha, relu, rowdeg, Cp2, ldc2, statadd, bnidx);
}

extern "C" void kernel_launch(void* const* d_in, const int* in_sizes, int n_in,
                              void* d_out, int out_size)
{
    const float* x         = (const float*)d_in[0];
    const int*   ei        = (const int*)  d_in[1];
    const int*   batch     = (const int*)  d_in[2];
    const float* proj_W    = (const float*)d_in[3];
    const float* proj_b    = (const float*)d_in[4];
    const float* gcn_W     = (const float*)d_in[5];
    const float* gcn_b     = (const float*)d_in[6];
    const float* qkv_w     = (const float*)d_in[7];
    const float* qkv_b     = (const float*)d_in[8];
    const float* out_w     = (const float*)d_in[9];
    const float* out_b     = (const float*)d_in[10];
    const float* bn_gamma  = (const float*)d_in[11];
    const float* bn_beta   = (const float*)d_in[12];
    const float* mlp_W1    = (const float*)d_in[13];
    const float* mlp_b1    = (const float*)d_in[14];
    const float* mlp_W2    = (const float*)d_in[15];
    const float* mlp_b2    = (const float*)d_in[16];
    const float* lin_W     = (const float*)d_in[17];
    const float* lin_b     = (const float*)d_in[18];
    float*       out       = (float*)d_out;

    const int* e_src = ei;
    const int* e_dst = ei + E_EDGES;

    float *p_h, *p_t2, *p_gcn, *p_hl, *p_ha, *p_o, *p_m1, *p_qkv, *p_attno, *p_deg;
    cudaGetSymbolAddress((void**)&p_h, g_h);
    cudaGetSymbolAddress((void**)&p_t2, g_t2);
    cudaGetSymbolAddress((void**)&p_gcn, g_gcnacc);
    cudaGetSymbolAddress((void**)&p_hl, g_hl);
    cudaGetSymbolAddress((void**)&p_ha, g_ha);
    cudaGetSymbolAddress((void**)&p_o, g_o);
    cudaGetSymbolAddress((void**)&p_m1, g_m1);
    cudaGetSymbolAddress((void**)&p_qkv, g_qkv);
    cudaGetSymbolAddress((void**)&p_attno, g_attno);
    cudaGetSymbolAddress((void**)&p_deg, g_deg);

    cudaFuncSetAttribute(flash_attn, cudaFuncAttributeMaxDynamicSharedMemorySize, FLASH_SMEM);

    static cudaStream_t sB = nullptr;
    static cudaEvent_t evFork[2], evJoin[2], evZ;
    if (!sB) {
        cudaStreamCreateWithFlags(&sB, cudaStreamNonBlocking);
        for (int i = 0; i < 2; i++) {
            cudaEventCreateWithFlags(&evFork[i], cudaEventDisableTiming);
            cudaEventCreateWithFlags(&evJoin[i], cudaEventDisableTiming);
        }
        cudaEventCreateWithFlags(&evZ, cudaEventDisableTiming);
    }
    cudaStream_t s0 = 0;

    const int NC4 = N_NODES * C_DIM / 4;

    zero_init<<<(G_GRAPHS * C_DIM + 255) / 256, 256, 0, s0>>>();
    cudaEventRecord(evZ, s0);
    cudaStreamWaitEvent(sB, evZ, 0);
    deg_scatter<<<(E_EDGES + 255) / 256, 256, 0, sB>>>(e_dst, batch);

    gemm_s(s0, x, 16, proj_W, C_DIM, 0, p_h, C_DIM, N_NODES, C_DIM, 16, proj_b, 1.f, 0);

    for (int l = 0; l < 2; l++) {
        const float* W_gcn  = gcn_W + (size_t)l * C_DIM * C_DIM;
        const float* b_gcn  = gcn_b + l * C_DIM;
        const float* W_qkv  = qkv_w + (size_t)l * 3 * C_DIM * C_DIM;
        const float* b_qkv  = qkv_b + l * 3 * C_DIM;
        const float* W_out  = out_w + (size_t)l * C_DIM * C_DIM;
        const float* b_out  = out_b + l * C_DIM;
        const float* W1     = mlp_W1 + (size_t)l * C_DIM * 2 * C_DIM;
        const float* b1     = mlp_b1 + l * 2 * C_DIM;
        const float* W2     = mlp_W2 + (size_t)l * 2 * C_DIM * C_DIM;
        const float* b2     = mlp_b2 + l * C_DIM;
        const float* gam    = bn_gamma + (size_t)l * 3 * C_DIM;
        const float* bet    = bn_beta  + (size_t)l * 3 * C_DIM;
        int bn0 = l * 3, bn1 = l * 3 + 1, bn2 = l * 3 + 2;

        // ==== fork: GCN branch on stream B, MHA branch on stream 0 ====
        cudaEventRecord(evFork[l], s0);
        cudaStreamWaitEvent(sB, evFork[l], 0);

        // ---- GCN branch (stream B)
        gemm_s(sB, p_h, C_DIM, W_gcn, C_DIM, 0, p_gcn, C_DIM, N_NODES, C_DIM, C_DIM,
               b_gcn, 1.f, 0, p_deg, p_m1, C_DIM);
        gcn_scatter<<<(E_EDGES * 32) / 256, 256, 0, sB>>>(e_src, e_dst, p_m1);
        bn_stats<<<N_NODES / 32, 128, 0, sB>>>(p_gcn, p_h, bn0);
        bn_apply<<<(NC4 + 255) / 256, 256, 0, sB>>>(p_gcn, p_h, gam, bet, p_hl, 0, bn0,
                                                    nullptr, nullptr, nullptr, 0);
        cudaEventRecord(evJoin[l], sB);

        // ---- MHA branch (stream 0)
        gemm_s(s0, p_h, C_DIM, W_qkv, C_DIM, 1, p_qkv, 3 * C_DIM, N_NODES, 3 * C_DIM, C_DIM,
               b_qkv, 1.f, 0);
        flash_attn<<<dim3(64, 2, NSPLIT), 128, FLASH_SMEM, s0>>>(p_qkv);
        merge_attn<<<(NC4 + 255) / 256, 256, 0, s0>>>();
        gemm_s(s0, p_attno, C_DIM, W_out, C_DIM, 1, p_t2, C_DIM, N_NODES, C_DIM, C_DIM,
               b_out, 1.f, 0, nullptr, nullptr, 0, p_h, bn1);

        // ==== join ====
        cudaStreamWaitEvent(s0, evJoin[l], 0);

        bn_apply<<<(NC4 + 255) / 256, 256, 0, s0>>>(p_t2, p_h, gam + C_DIM, bet + C_DIM, p_ha, 0, bn1,
                                                    p_hl, p_o, nullptr, 0);

        // ---- MLP (stream 0)
        gemm_s(s0, p_o, C_DIM, W1, 2 * C_DIM, 0, p_m1, 2 * C_DIM, N_NODES, 2 * C_DIM, C_DIM,
               b1, 1.f, 1);
        gemm_s(s0, p_m1, 2 * C_DIM, W2, C_DIM, 0, p_t2, C_DIM, N_NODES, C_DIM, 2 * C_DIM,
               b2, 1.f, 0, nullptr, nullptr, 0, p_o, bn2);
        bn_apply<<<(NC4 + 255) / 256, 256, 0, s0>>>(p_o, p_t2, gam + 2 * C_DIM, bet + 2 * C_DIM, p_h,
                                                    l == 0 ? 1 : 0, bn2,
                                                    nullptr, nullptr, batch, l == 1 ? 1 : 0);
    }

    final_kernel<<<G_GRAPHS, C_DIM, 0, s0>>>(lin_W, lin_b, out);
}

// round 12
// speedup vs baseline: 1.3133x; 1.0428x over previous
#include <cuda_runtime.h>
#include <math.h>
#include <stdint.h>

#define N_NODES  4096
#define C_DIM    128
#define H_HEADS  2
#define D_HEAD   64
#define E_EDGES  131072
#define G_GRAPHS 64
#define N_CLASSES 4
#define BN_EPS   1e-5f
#define NSPLIT   4

// ---------------- scratch ----------------------------------------------------
static __device__ float g_h[N_NODES * C_DIM];
static __device__ float g_t2[N_NODES * C_DIM];
static __device__ float g_gcnacc[N_NODES * C_DIM];
static __device__ float g_hl[N_NODES * C_DIM];
static __device__ float g_ha[N_NODES * C_DIM];
static __device__ float g_o[N_NODES * C_DIM];
static __device__ float g_m1[N_NODES * 2 * C_DIM];
static __device__ float g_qkv[N_NODES * 3 * C_DIM];
static __device__ float g_attno[N_NODES * C_DIM];
static __device__ float g_opart[NSPLIT * N_NODES * C_DIM];
static __device__ float g_ml[NSPLIT * N_NODES * H_HEADS * 2];
static __device__ float g_sum[6 * C_DIM];
static __device__ float g_sumsq[6 * C_DIM];
static __device__ float g_pool[G_GRAPHS * C_DIM];
static __device__ float g_cnt[G_GRAPHS];
// CSR
static __device__ int g_ecnt[N_NODES];
static __device__ int g_fill[N_NODES];
static __device__ int g_rowstart[N_NODES + 1];
static __device__ int g_colidx[E_EDGES];

// ---------------- tf32 / atomic helpers -------------------------------------
__device__ __forceinline__ uint32_t f2tf32(float f) {
    uint32_t u;
    asm volatile("cvt.rna.tf32.f32 %0, %1;\n" : "=r"(u) : "f"(f));
    return u;
}
__device__ __forceinline__ float f2tf32f(float f) {
    return __uint_as_float(f2tf32(f));
}

__device__ __forceinline__ void mma_tf32(float c[4], const uint32_t a[4], const uint32_t b[2]) {
    asm volatile(
        "mma.sync.aligned.m16n8k8.row.col.f32.tf32.tf32.f32 "
        "{%0,%1,%2,%3}, {%4,%5,%6,%7}, {%8,%9}, {%0,%1,%2,%3};\n"
        : "+f"(c[0]), "+f"(c[1]), "+f"(c[2]), "+f"(c[3])
        : "r"(a[0]), "r"(a[1]), "r"(a[2]), "r"(a[3]), "r"(b[0]), "r"(b[1]));
}

__device__ __forceinline__ void red_add_v4(float* p, float a, float b, float c, float d) {
    asm volatile("red.global.add.v4.f32 [%0], {%1,%2,%3,%4};\n"
                 :: "l"(p), "f"(a), "f"(b), "f"(c), "f"(d) : "memory");
}

__device__ __forceinline__ void cp_async16(const float* smem, const float* g) {
    uint32_t s = (uint32_t)__cvta_generic_to_shared(smem);
    asm volatile("cp.async.ca.shared.global [%0], [%1], 16;\n" :: "r"(s), "l"(g));
}
__device__ __forceinline__ void cp_commit() {
    asm volatile("cp.async.commit_group;\n");
}
template <int Np>
__device__ __forceinline__ void cp_wait() {
    asm volatile("cp.async.wait_group %0;\n" :: "n"(Np));
}

// ---------------- tensor-core SGEMM (tf32), 8 warps --------------------------
#define TSTRIDE 36

__global__ __launch_bounds__(256) void tgemm_kernel(
    const float* __restrict__ A, int lda,
    const float* __restrict__ B, int ldb, int transB,
    float* __restrict__ Cp, int ldc,
    int M, int Nc, int K,
    const float* __restrict__ bias, float alpha, int relu,
    const float* __restrict__ statadd, int bnidx)
{
    __shared__ float As[64 * TSTRIDE];
    __shared__ float Bs[64 * TSTRIDE];

    const int tid  = threadIdx.x;
    const int lane = tid & 31;
    const int w    = tid >> 5;
    const int wm   = w & 3;
    const int wn   = w >> 2;
    const int r    = lane >> 2;
    const int cq   = lane & 3;
    const int m0   = blockIdx.y * 64;
    const int n0   = blockIdx.x * 64;

    float acc[4][4];
#pragma unroll
    for (int nt = 0; nt < 4; nt++)
#pragma unroll
        for (int i = 0; i < 4; i++) acc[nt][i] = 0.f;

    for (int k0 = 0; k0 < K; k0 += 32) {
#pragma unroll
        for (int i = 0; i < 8; i++) {
            int idx = tid + i * 256;
            int k = idx & 31, row = idx >> 5;
            int gk = k0 + k;
            float v = (gk < K) ? A[(size_t)(m0 + row) * lda + gk] : 0.f;
            As[row * TSTRIDE + k] = f2tf32f(v);
        }
        if (transB) {
#pragma unroll
            for (int i = 0; i < 8; i++) {
                int idx = tid + i * 256;
                int k = idx & 31, n = idx >> 5;
                int gk = k0 + k;
                float v = (gk < K) ? B[(size_t)(n0 + n) * ldb + gk] : 0.f;
                Bs[n * TSTRIDE + k] = f2tf32f(v);
            }
        } else {
#pragma unroll
            for (int i = 0; i < 8; i++) {
                int idx = tid + i * 256;
                int n = idx & 63, k = idx >> 6;
                int gk = k0 + k;
                float v = (gk < K) ? B[(size_t)gk * ldb + n0 + n] : 0.f;
                Bs[n * TSTRIDE + k] = f2tf32f(v);
            }
        }
        __syncthreads();

        uint32_t a[4][4];
#pragma unroll
        for (int kf = 0; kf < 4; kf++) {
            const float* ar0 = As + (16 * wm + r) * TSTRIDE + 8 * kf;
            const float* ar1 = As + (16 * wm + r + 8) * TSTRIDE + 8 * kf;
            a[kf][0] = __float_as_uint(ar0[cq]);
            a[kf][1] = __float_as_uint(ar1[cq]);
            a[kf][2] = __float_as_uint(ar0[cq + 4]);
            a[kf][3] = __float_as_uint(ar1[cq + 4]);
        }
#pragma unroll
        for (int nt = 0; nt < 4; nt++) {
            const float* br = Bs + (32 * wn + 8 * nt + r) * TSTRIDE;
#pragma unroll
            for (int kf = 0; kf < 4; kf++) {
                uint32_t b[2];
                b[0] = __float_as_uint(br[8 * kf + cq]);
                b[1] = __float_as_uint(br[8 * kf + cq + 4]);
                mma_tf32(acc[nt], a[kf], b);
            }
        }
        __syncthreads();
    }

    int row0 = m0 + 16 * wm + r;
    int row1 = row0 + 8;

    float csum[4][2], csq[4][2];
#pragma unroll
    for (int nt = 0; nt < 4; nt++) {
        int gn = n0 + 32 * wn + 8 * nt + 2 * cq;
        float b0 = bias ? bias[gn] : 0.f;
        float b1 = bias ? bias[gn + 1] : 0.f;
        float v00 = alpha * acc[nt][0] + b0;
        float v01 = alpha * acc[nt][1] + b1;
        float v10 = alpha * acc[nt][2] + b0;
        float v11 = alpha * acc[nt][3] + b1;
        if (bnidx >= 0) {
            float2 a0 = *(const float2*)(statadd + (size_t)row0 * 128 + gn);
            float2 a1 = *(const float2*)(statadd + (size_t)row1 * 128 + gn);
            float s00 = v00 + a0.x, s01 = v01 + a0.y;
            float s10 = v10 + a1.x, s11 = v11 + a1.y;
            csum[nt][0] = s00 + s10;
            csum[nt][1] = s01 + s11;
            csq[nt][0]  = s00 * s00 + s10 * s10;
            csq[nt][1]  = s01 * s01 + s11 * s11;
        }
        if (relu) {
            v00 = fmaxf(v00, 0.f); v01 = fmaxf(v01, 0.f);
            v10 = fmaxf(v10, 0.f); v11 = fmaxf(v11, 0.f);
        }
        *(float2*)(Cp + (size_t)row0 * ldc + gn) = make_float2(v00, v01);
        *(float2*)(Cp + (size_t)row1 * ldc + gn) = make_float2(v10, v11);
    }

    if (bnidx >= 0) {
#pragma unroll
        for (int nt = 0; nt < 4; nt++)
#pragma unroll
            for (int j = 0; j < 2; j++) {
#pragma unroll
                for (int msk = 4; msk <= 16; msk <<= 1) {
                    csum[nt][j] += __shfl_xor_sync(0xffffffffu, csum[nt][j], msk);
                    csq[nt][j]  += __shfl_xor_sync(0xffffffffu, csq[nt][j], msk);
                }
            }
        if (lane < 4) {
#pragma unroll
            for (int nt = 0; nt < 4; nt++) {
                int gn = n0 + 32 * wn + 8 * nt + 2 * cq;
                atomicAdd(&g_sum[bnidx * C_DIM + gn],     csum[nt][0]);
                atomicAdd(&g_sum[bnidx * C_DIM + gn + 1], csum[nt][1]);
                atomicAdd(&g_sumsq[bnidx * C_DIM + gn],     csq[nt][0]);
                atomicAdd(&g_sumsq[bnidx * C_DIM + gn + 1], csq[nt][1]);
            }
        }
    }
}

// ---------------- split-KV flash attention (4 splits, 64 q-rows) ------------
#define KSTRIDE 68
#define VSTRIDE 72
#define KSZ (64 * KSTRIDE)
#define VSZ (64 * VSTRIDE)
#define ML_IDX(sp, row, h) ((((sp) * N_NODES + (row)) * H_HEADS + (h)) * 2)

__global__ __launch_bounds__(128) void flash_attn(
    const float* __restrict__ qkv)
{
    extern __shared__ float sm[];
    float* Kb[2] = { sm, sm + KSZ };
    float* Vb[2] = { sm + 2 * KSZ, sm + 2 * KSZ + VSZ };
    float* Ps    = sm + 2 * KSZ + 2 * VSZ;
    float* Qs    = sm;

    const int tid  = threadIdx.x;
    const int lane = tid & 31;
    const int w    = tid >> 5;
    const int r    = lane >> 2;
    const int cq   = lane & 3;

    const int h    = blockIdx.y;
    const int m0   = blockIdx.x * 64;
    const int sp   = blockIdx.z;
    const int j0   = sp * (64 / NSPLIT);
    const int qoff = h * D_HEAD;
    const int koff = C_DIM + h * D_HEAD;
    const int voff = 2 * C_DIM + h * D_HEAD;

#pragma unroll
    for (int i = 0; i < 8; i++) {
        int idx = tid + i * 128;
        int row = idx >> 4, c4 = idx & 15;
        cp_async16(Qs + row * KSTRIDE + c4 * 4,
                   qkv + (size_t)(m0 + row) * 384 + qoff + c4 * 4);
    }
    cp_commit();
    cp_wait<0>();
    __syncthreads();

    uint32_t qa[8][4];
#pragma unroll
    for (int kf = 0; kf < 8; kf++) {
        const float* qr0 = Qs + (16 * w + r) * KSTRIDE + 8 * kf;
        const float* qr1 = Qs + (16 * w + r + 8) * KSTRIDE + 8 * kf;
        qa[kf][0] = f2tf32(qr0[cq] * 0.125f);
        qa[kf][1] = f2tf32(qr1[cq] * 0.125f);
        qa[kf][2] = f2tf32(qr0[cq + 4] * 0.125f);
        qa[kf][3] = f2tf32(qr1[cq + 4] * 0.125f);
    }
    __syncthreads();

    {
        const float* kg = qkv + (size_t)j0 * 64 * 384 + koff;
        const float* vg = qkv + (size_t)j0 * 64 * 384 + voff;
#pragma unroll
        for (int i = 0; i < 8; i++) {
            int idx = tid + i * 128;
            int row = idx >> 4, c4 = idx & 15;
            cp_async16(Kb[0] + row * KSTRIDE + c4 * 4, kg + (size_t)row * 384 + c4 * 4);
            cp_async16(Vb[0] + row * VSTRIDE + c4 * 4, vg + (size_t)row * 384 + c4 * 4);
        }
        cp_commit();
    }

    float o[8][4];
#pragma unroll
    for (int dt = 0; dt < 8; dt++)
#pragma unroll
        for (int i = 0; i < 4; i++) o[dt][i] = 0.f;
    float mrun0 = -1e30f, mrun1 = -1e30f;
    float lrun0 = 0.f, lrun1 = 0.f;

    const int NBLK = 64 / NSPLIT;
    for (int j = 0; j < NBLK; j++) {
        if (j < NBLK - 1) {
            const float* kg = qkv + (size_t)(j0 + j + 1) * 64 * 384 + koff;
            const float* vg = qkv + (size_t)(j0 + j + 1) * 64 * 384 + voff;
            float* kd = Kb[(j + 1) & 1];
            float* vd = Vb[(j + 1) & 1];
#pragma unroll
            for (int i = 0; i < 8; i++) {
                int idx = tid + i * 128;
                int row = idx >> 4, c4 = idx & 15;
                cp_async16(kd + row * KSTRIDE + c4 * 4, kg + (size_t)row * 384 + c4 * 4);
                cp_async16(vd + row * VSTRIDE + c4 * 4, vg + (size_t)row * 384 + c4 * 4);
            }
            cp_commit();
            cp_wait<1>();
        } else {
            cp_wait<0>();
        }
        __syncthreads();

        const float* Kt = Kb[j & 1];
        const float* Vt = Vb[j & 1];

        float s[8][4];
#pragma unroll
        for (int nt = 0; nt < 8; nt++) {
            s[nt][0] = 0.f; s[nt][1] = 0.f; s[nt][2] = 0.f; s[nt][3] = 0.f;
            const float* kr = Kt + (8 * nt + r) * KSTRIDE;
#pragma unroll
            for (int kf = 0; kf < 8; kf++) {
                uint32_t b[2];
                b[0] = __float_as_uint(kr[8 * kf + cq]);
                b[1] = __float_as_uint(kr[8 * kf + cq + 4]);
                mma_tf32(s[nt], qa[kf], b);
            }
        }

        float mx0 = -1e30f, mx1 = -1e30f;
#pragma unroll
        for (int nt = 0; nt < 8; nt++) {
            mx0 = fmaxf(mx0, fmaxf(s[nt][0], s[nt][1]));
            mx1 = fmaxf(mx1, fmaxf(s[nt][2], s[nt][3]));
        }
        mx0 = fmaxf(mx0, __shfl_xor_sync(0xffffffffu, mx0, 1));
        mx0 = fmaxf(mx0, __shfl_xor_sync(0xffffffffu, mx0, 2));
        mx1 = fmaxf(mx1, __shfl_xor_sync(0xffffffffu, mx1, 1));
        mx1 = fmaxf(mx1, __shfl_xor_sync(0xffffffffu, mx1, 2));

        float mnew0 = fmaxf(mrun0, mx0);
        float mnew1 = fmaxf(mrun1, mx1);
        float f0 = __expf(mrun0 - mnew0);
        float f1 = __expf(mrun1 - mnew1);
        mrun0 = mnew0; mrun1 = mnew1;

        float sum0 = 0.f, sum1 = 0.f;
        float* pw = Ps + (16 * w) * KSTRIDE;
#pragma unroll
        for (int nt = 0; nt < 8; nt++) {
            float p0 = __expf(s[nt][0] - mnew0);
            float p1 = __expf(s[nt][1] - mnew0);
            float p2 = __expf(s[nt][2] - mnew1);
            float p3 = __expf(s[nt][3] - mnew1);
            sum0 += p0 + p1;
            sum1 += p2 + p3;
            float2* d0 = (float2*)(pw + r * KSTRIDE + 8 * nt + 2 * cq);
            float2* d1 = (float2*)(pw + (r + 8) * KSTRIDE + 8 * nt + 2 * cq);
            *d0 = make_float2(f2tf32f(p0), f2tf32f(p1));
            *d1 = make_float2(f2tf32f(p2), f2tf32f(p3));
        }
        sum0 += __shfl_xor_sync(0xffffffffu, sum0, 1);
        sum0 += __shfl_xor_sync(0xffffffffu, sum0, 2);
        sum1 += __shfl_xor_sync(0xffffffffu, sum1, 1);
        sum1 += __shfl_xor_sync(0xffffffffu, sum1, 2);
        lrun0 = lrun0 * f0 + sum0;
        lrun1 = lrun1 * f1 + sum1;

#pragma unroll
        for (int dt = 0; dt < 8; dt++) {
            o[dt][0] *= f0; o[dt][1] *= f0;
            o[dt][2] *= f1; o[dt][3] *= f1;
        }
        __syncwarp();

#pragma unroll
        for (int kf = 0; kf < 8; kf++) {
            uint32_t pa[4];
            pa[0] = __float_as_uint(pw[r * KSTRIDE + 8 * kf + cq]);
            pa[1] = __float_as_uint(pw[(r + 8) * KSTRIDE + 8 * kf + cq]);
            pa[2] = __float_as_uint(pw[r * KSTRIDE + 8 * kf + cq + 4]);
            pa[3] = __float_as_uint(pw[(r + 8) * KSTRIDE + 8 * kf + cq + 4]);
            const float* v0 = Vt + (8 * kf + cq) * VSTRIDE;
            const float* v1 = Vt + (8 * kf + cq + 4) * VSTRIDE;
#pragma unroll
            for (int dt = 0; dt < 8; dt++) {
                uint32_t b[2];
                b[0] = __float_as_uint(v0[8 * dt + r]);
                b[1] = __float_as_uint(v1[8 * dt + r]);
                mma_tf32(o[dt], pa, b);
            }
        }
        __syncthreads();
    }

    int row0 = m0 + 16 * w + r;
    int row1 = row0 + 8;
    float* orow0 = g_opart + (size_t)sp * N_NODES * C_DIM + (size_t)row0 * C_DIM + h * D_HEAD;
    float* orow1 = g_opart + (size_t)sp * N_NODES * C_DIM + (size_t)row1 * C_DIM + h * D_HEAD;
#pragma unroll
    for (int dt = 0; dt < 8; dt++) {
        *(float2*)(orow0 + 8 * dt + 2 * cq) = make_float2(o[dt][0], o[dt][1]);
        *(float2*)(orow1 + 8 * dt + 2 * cq) = make_float2(o[dt][2], o[dt][3]);
    }
    if (cq == 0) {
        int i0 = ML_IDX(sp, row0, h);
        int i1 = ML_IDX(sp, row1, h);
        g_ml[i0] = mrun0; g_ml[i0 + 1] = lrun0;
        g_ml[i1] = mrun1; g_ml[i1 + 1] = lrun1;
    }
}

#define FLASH_SMEM ((2 * KSZ + 2 * VSZ + KSZ) * 4)

// merge NSPLIT KV splits (exact fp32)
__global__ void merge_attn()
{
    int t = blockIdx.x * blockDim.x + threadIdx.x;
    if (t >= N_NODES * C_DIM / 4) return;
    int row = t >> 5;
    int c4  = t & 31;
    int h   = c4 >> 4;

    float m = -1e30f;
    float mv[NSPLIT], lv[NSPLIT];
#pragma unroll
    for (int s = 0; s < NSPLIT; s++) {
        int i = ML_IDX(s, row, h);
        mv[s] = g_ml[i]; lv[s] = g_ml[i + 1];
        m = fmaxf(m, mv[s]);
    }
    float wsum = 0.f, wv[NSPLIT];
#pragma unroll
    for (int s = 0; s < NSPLIT; s++) {
        wv[s] = __expf(mv[s] - m);
        wsum += wv[s] * lv[s];
    }
    float inv = 1.f / wsum;

    float4 acc = make_float4(0.f, 0.f, 0.f, 0.f);
#pragma unroll
    for (int s = 0; s < NSPLIT; s++) {
        float4 ov = ((const float4*)(g_opart + (size_t)s * N_NODES * C_DIM + (size_t)row * C_DIM))[c4];
        acc.x += wv[s] * ov.x;
        acc.y += wv[s] * ov.y;
        acc.z += wv[s] * ov.z;
        acc.w += wv[s] * ov.w;
    }
    acc.x *= inv; acc.y *= inv; acc.z *= inv; acc.w *= inv;
    ((float4*)(g_attno + (size_t)row * C_DIM))[c4] = acc;
}

// ---------------- init / CSR / BN --------------------------------------------
__global__ void zero_init()
{
    int i = blockIdx.x * blockDim.x + threadIdx.x;
    if (i < 6 * C_DIM) { g_sum[i] = 0.f; g_sumsq[i] = 0.f; }
    if (i < G_GRAPHS * C_DIM) g_pool[i] = 0.f;
    if (i < G_GRAPHS) g_cnt[i] = 0.f;
    if (i < N_NODES) { g_ecnt[i] = 0; g_fill[i] = 0; }
}

// edge counting + graph-count scatter
__global__ void csr_count(const int* __restrict__ dst, const int* __restrict__ batch)
{
    int e = blockIdx.x * blockDim.x + threadIdx.x;
    if (e < E_EDGES) atomicAdd(&g_ecnt[dst[e]], 1);
    if (e < N_NODES) atomicAdd(&g_cnt[batch[e]], 1.f);
}

// single-block prefix scan (1024 threads, 4 elems each)
__global__ __launch_bounds__(1024) void csr_prefix()
{
    __shared__ int sh[1024];
    int tid = threadIdx.x;
    int base = tid * 4;
    int s0 = g_ecnt[base], s1 = g_ecnt[base + 1], s2 = g_ecnt[base + 2], s3 = g_ecnt[base + 3];
    int tsum = s0 + s1 + s2 + s3;
    sh[tid] = tsum;
    __syncthreads();
    for (int off = 1; off < 1024; off <<= 1) {
        int v = (tid >= off) ? sh[tid - off] : 0;
        __syncthreads();
        sh[tid] += v;
        __syncthreads();
    }
    int pre = tid ? sh[tid - 1] : 0;
    g_rowstart[base]     = pre;
    g_rowstart[base + 1] = pre + s0;
    g_rowstart[base + 2] = pre + s0 + s1;
    g_rowstart[base + 3] = pre + s0 + s1 + s2;
    if (tid == 1023) g_rowstart[N_NODES] = pre + tsum;
}

__global__ void csr_fill(const int* __restrict__ src, const int* __restrict__ dst)
{
    int e = blockIdx.x * blockDim.x + threadIdx.x;
    if (e >= E_EDGES) return;
    int d = dst[e];
    int pos = atomicAdd(&g_fill[d], 1);
    g_colidx[g_rowstart[d] + pos] = src[e];
}

// ---------------- GCN gather (warp per node, no atomics) ---------------------
__global__ __launch_bounds__(256) void gcn_gather(
    const float* __restrict__ t1, const float* __restrict__ bias)
{
    int gid = blockIdx.x * blockDim.x + threadIdx.x;
    int n = gid >> 5;
    int lane = gid & 31;
    if (n >= N_NODES) return;

    int beg = g_rowstart[n], end = g_rowstart[n + 1];
    float degn = (float)(end - beg + 1);
    float rn = rsqrtf(degn);
    float invn = 1.f / degn;

    const float4* t14 = (const float4*)t1;
    float4 self = t14[(size_t)n * 32 + lane];
    float4 acc = make_float4(self.x * invn, self.y * invn, self.z * invn, self.w * invn);

    for (int e = beg; e < end; e++) {
        int s = g_colidx[e];
        float coef = rn * rsqrtf((float)(g_ecnt[s] + 1));
        float4 v = t14[(size_t)s * 32 + lane];
        acc.x += v.x * coef;
        acc.y += v.y * coef;
        acc.z += v.z * coef;
        acc.w += v.w * coef;
    }
    float4 b = *(const float4*)(bias + lane * 4);
    acc.x += b.x; acc.y += b.y; acc.z += b.z; acc.w += b.w;
    ((float4*)g_gcnacc)[(size_t)n * 32 + lane] = acc;
}

__global__ void bn_stats(const float* __restrict__ a, const float* __restrict__ b, int bn)
{
    int c = threadIdx.x;
    int r0 = blockIdx.x * 32;
    float s = 0.f, s2 = 0.f;
#pragma unroll 4
    for (int r = 0; r < 32; r++) {
        int i = (r0 + r) * C_DIM + c;
        float v = a[i] + b[i];
        s += v; s2 += v * v;
    }
    atomicAdd(&g_sum[bn * C_DIM + c], s);
    atomicAdd(&g_sumsq[bn * C_DIM + c], s2);
}

__global__ void bn_apply(const float* __restrict__ a, const float* __restrict__ b,
                         const float* __restrict__ gamma, const float* __restrict__ beta,
                         float* __restrict__ out, int relu, int bn,
                         const float* __restrict__ addin, float* __restrict__ addout,
                         const int* __restrict__ batch, int dopool)
{
    int t = blockIdx.x * blockDim.x + threadIdx.x;
    if (t >= N_NODES * C_DIM / 4) return;
    int row = t >> 5;
    int c4  = t & 31;
    int c   = c4 * 4;

    float4 va = ((const float4*)a)[t];
    float4 vb = ((const float4*)b)[t];
    float4 vg = *(const float4*)(gamma + c);
    float4 vbt = *(const float4*)(beta + c);
    float4 vsum = *(const float4*)(g_sum + bn * C_DIM + c);
    float4 vsq  = *(const float4*)(g_sumsq + bn * C_DIM + c);

    float4 v;
    {
        float mu, var, rsig, x;
        mu = vsum.x * (1.f / N_NODES); var = vsq.x * (1.f / N_NODES) - mu * mu;
        rsig = rsqrtf(var + BN_EPS); x = va.x + vb.x; v.x = (x - mu) * rsig * vg.x + vbt.x;
        mu = vsum.y * (1.f / N_NODES); var = vsq.y * (1.f / N_NODES) - mu * mu;
        rsig = rsqrtf(var + BN_EPS); x = va.y + vb.y; v.y = (x - mu) * rsig * vg.y + vbt.y;
        mu = vsum.z * (1.f / N_NODES); var = vsq.z * (1.f / N_NODES) - mu * mu;
        rsig = rsqrtf(var + BN_EPS); x = va.z + vb.z; v.z = (x - mu) * rsig * vg.z + vbt.z;
        mu = vsum.w * (1.f / N_NODES); var = vsq.w * (1.f / N_NODES) - mu * mu;
        rsig = rsqrtf(var + BN_EPS); x = va.w + vb.w; v.w = (x - mu) * rsig * vg.w + vbt.w;
    }
    if (relu) {
        v.x = fmaxf(v.x, 0.f); v.y = fmaxf(v.y, 0.f);
        v.z = fmaxf(v.z, 0.f); v.w = fmaxf(v.w, 0.f);
    }
    ((float4*)out)[t] = v;
    if (addout) {
        float4 vi = ((const float4*)addin)[t];
        float4 vo = make_float4(v.x + vi.x, v.y + vi.y, v.z + vi.z, v.w + vi.w);
        ((float4*)addout)[t] = vo;
    }
    if (dopool) {
        int g = batch[row];
        red_add_v4(g_pool + g * C_DIM + c, v.x, v.y, v.z, v.w);
    }
}

// ---------------- classifier -------------------------------------------------
__global__ void final_kernel(const float* __restrict__ linW,
                             const float* __restrict__ linb,
                             float* __restrict__ out)
{
    __shared__ float sh[C_DIM];
    int g = blockIdx.x;
    int tid = threadIdx.x;
    float cnt = fmaxf(g_cnt[g], 1.f);
    sh[tid] = g_pool[g * C_DIM + tid] / cnt;
    __syncthreads();
    if (tid < N_CLASSES) {
        float acc = linb[tid];
#pragma unroll 4
        for (int c = 0; c < C_DIM; c++)
            acc += sh[c] * linW[c * N_CLASSES + tid];
        out[g * N_CLASSES + tid] = acc;
    }
}

// ---------------- host side --------------------------------------------------
static inline void gemm_s(cudaStream_t st,
                          const float* A, int lda, const float* B, int ldb, int transB,
                          float* Cp, int ldc, int M, int Nc, int K,
                          const float* bias, float alpha, int relu,
                          const float* statadd = nullptr, int bnidx = -1)
{
    dim3 grid((Nc + 63) / 64, (M + 63) / 64);
    tgemm_kernel<<<grid, 256, 0, st>>>(A, lda, B, ldb, transB, Cp, ldc, M, Nc, K,
                                       bias, alpha, relu, statadd, bnidx);
}

extern "C" void kernel_launch(void* const* d_in, const int* in_sizes, int n_in,
                              void* d_out, int out_size)
{
    const float* x         = (const float*)d_in[0];
    const int*   ei        = (const int*)  d_in[1];
    const int*   batch     = (const int*)  d_in[2];
    const float* proj_W    = (const float*)d_in[3];
    const float* proj_b    = (const float*)d_in[4];
    const float* gcn_W     = (const float*)d_in[5];
    const float* gcn_b     = (const float*)d_in[6];
    const float* qkv_w     = (const float*)d_in[7];
    const float* qkv_b     = (const float*)d_in[8];
    const float* out_w     = (const float*)d_in[9];
    const float* out_b     = (const float*)d_in[10];
    const float* bn_gamma  = (const float*)d_in[11];
    const float* bn_beta   = (const float*)d_in[12];
    const float* mlp_W1    = (const float*)d_in[13];
    const float* mlp_b1    = (const float*)d_in[14];
    const float* mlp_W2    = (const float*)d_in[15];
    const float* mlp_b2    = (const float*)d_in[16];
    const float* lin_W     = (const float*)d_in[17];
    const float* lin_b     = (const float*)d_in[18];
    float*       out       = (float*)d_out;

    const int* e_src = ei;
    const int* e_dst = ei + E_EDGES;

    float *p_h, *p_t2, *p_gcn, *p_hl, *p_ha, *p_o, *p_m1, *p_qkv, *p_attno;
    cudaGetSymbolAddress((void**)&p_h, g_h);
    cudaGetSymbolAddress((void**)&p_t2, g_t2);
    cudaGetSymbolAddress((void**)&p_gcn, g_gcnacc);
    cudaGetSymbolAddress((void**)&p_hl, g_hl);
    cudaGetSymbolAddress((void**)&p_ha, g_ha);
    cudaGetSymbolAddress((void**)&p_o, g_o);
    cudaGetSymbolAddress((void**)&p_m1, g_m1);
    cudaGetSymbolAddress((void**)&p_qkv, g_qkv);
    cudaGetSymbolAddress((void**)&p_attno, g_attno);

    cudaFuncSetAttribute(flash_attn, cudaFuncAttributeMaxDynamicSharedMemorySize, FLASH_SMEM);

    static cudaStream_t sB = nullptr;
    static cudaEvent_t evFork[2], evJoin[2], evZ;
    if (!sB) {
        cudaStreamCreateWithFlags(&sB, cudaStreamNonBlocking);
        for (int i = 0; i < 2; i++) {
            cudaEventCreateWithFlags(&evFork[i], cudaEventDisableTiming);
            cudaEventCreateWithFlags(&evJoin[i], cudaEventDisableTiming);
        }
        cudaEventCreateWithFlags(&evZ, cudaEventDisableTiming);
    }
    cudaStream_t s0 = 0;

    const int NC4 = N_NODES * C_DIM / 4;

    zero_init<<<(G_GRAPHS * C_DIM + 255) / 256, 256, 0, s0>>>();
    cudaEventRecord(evZ, s0);
    // CSR build on stream B, overlapped with proj GEMM
    cudaStreamWaitEvent(sB, evZ, 0);
    csr_count<<<(E_EDGES + 255) / 256, 256, 0, sB>>>(e_dst, batch);
    csr_prefix<<<1, 1024, 0, sB>>>();
    csr_fill<<<(E_EDGES + 255) / 256, 256, 0, sB>>>(e_src, e_dst);

    gemm_s(s0, x, 16, proj_W, C_DIM, 0, p_h, C_DIM, N_NODES, C_DIM, 16, proj_b, 1.f, 0);

    for (int l = 0; l < 2; l++) {
        const float* W_gcn  = gcn_W + (size_t)l * C_DIM * C_DIM;
        const float* b_gcn  = gcn_b + l * C_DIM;
        const float* W_qkv  = qkv_w + (size_t)l * 3 * C_DIM * C_DIM;
        const float* b_qkv  = qkv_b + l * 3 * C_DIM;
        const float* W_out  = out_w + (size_t)l * C_DIM * C_DIM;
        const float* b_out  = out_b + l * C_DIM;
        const float* W1     = mlp_W1 + (size_t)l * C_DIM * 2 * C_DIM;
        const float* b1     = mlp_b1 + l * 2 * C_DIM;
        const float* W2     = mlp_W2 + (size_t)l * 2 * C_DIM * C_DIM;
        const float* b2     = mlp_b2 + l * C_DIM;
        const float* gam    = bn_gamma + (size_t)l * 3 * C_DIM;
        const float* bet    = bn_beta  + (size_t)l * 3 * C_DIM;
        int bn0 = l * 3, bn1 = l * 3 + 1, bn2 = l * 3 + 2;

        // ==== fork: GCN branch on stream B, MHA branch on stream 0 ====
        cudaEventRecord(evFork[l], s0);
        cudaStreamWaitEvent(sB, evFork[l], 0);

        // ---- GCN branch (stream B): m1 = h@W ; gather (CSR, no atomics)
        gemm_s(sB, p_h, C_DIM, W_gcn, C_DIM, 0, p_m1, C_DIM, N_NODES, C_DIM, C_DIM,
               nullptr, 1.f, 0);
        gcn_gather<<<(N_NODES * 32 + 255) / 256, 256, 0, sB>>>(p_m1, b_gcn);
        bn_stats<<<N_NODES / 32, 128, 0, sB>>>(p_gcn, p_h, bn0);
        bn_apply<<<(NC4 + 255) / 256, 256, 0, sB>>>(p_gcn, p_h, gam, bet, p_hl, 0, bn0,
                                                    nullptr, nullptr, nullptr, 0);
        cudaEventRecord(evJoin[l], sB);

        // ---- MHA branch (stream 0)
        gemm_s(s0, p_h, C_DIM, W_qkv, C_DIM, 1, p_qkv, 3 * C_DIM, N_NODES, 3 * C_DIM, C_DIM,
               b_qkv, 1.f, 0);
        flash_attn<<<dim3(64, 2, NSPLIT), 128, FLASH_SMEM, s0>>>(p_qkv);
        merge_attn<<<(NC4 + 255) / 256, 256, 0, s0>>>();
        gemm_s(s0, p_attno, C_DIM, W_out, C_DIM, 1, p_t2, C_DIM, N_NODES, C_DIM, C_DIM,
               b_out, 1.f, 0, p_h, bn1);

        // ==== join ====
        cudaStreamWaitEvent(s0, evJoin[l], 0);

        bn_apply<<<(NC4 + 255) / 256, 256, 0, s0>>>(p_t2, p_h, gam + C_DIM, bet + C_DIM, p_ha, 0, bn1,
                                                    p_hl, p_o, nullptr, 0);

        // ---- MLP (stream 0)
        gemm_s(s0, p_o, C_DIM, W1, 2 * C_DIM, 0, p_m1, 2 * C_DIM, N_NODES, 2 * C_DIM, C_DIM,
               b1, 1.f, 1);
        gemm_s(s0, p_m1, 2 * C_DIM, W2, C_DIM, 0, p_t2, C_DIM, N_NODES, C_DIM, 2 * C_DIM,
               b2, 1.f, 0, p_o, bn2);
        bn_apply<<<(NC4 + 255) / 256, 256, 0, s0>>>(p_o, p_t2, gam + 2 * C_DIM, bet + 2 * C_DIM, p_h,
                                                    l == 0 ? 1 : 0, bn2,
                                                    nullptr, nullptr, batch, l == 1 ? 1 : 0);
    }

    final_kernel<<<G_GRAPHS, C_DIM, 0, s0>>>(lin_W, lin_b, out);
}